// round 14
// baseline (speedup 1.0000x reference)
#include <cuda_runtime.h>
#include <cuda_bf16.h>
#include <stdint.h>
#include <math.h>

#define F_DIM 257
#define T_DIM 257
#define NB 4
#define NPIX (F_DIM * T_DIM)        // 66049
#define NTOT (NB * NPIX)            // 264196
#define SLOPE 0.2f

// ======================= scratch =======================
__device__ float d_h[NB * 2 * NPIX];                                // STFT (B,2,F,T)
__device__ __align__(16) unsigned short d_a0h[(size_t)NTOT * 64];   // NHWC bf16 hi
__device__ __align__(16) unsigned short d_a0l[(size_t)NTOT * 64];   // NHWC bf16 lo
__device__ __align__(16) unsigned short d_a1h[(size_t)NTOT * 64];
__device__ __align__(16) unsigned short d_a1l[(size_t)NTOT * 64];
__device__ __align__(16) float d_afin[(size_t)NTOT * 64];           // final conv3 out, fp32 NHWC
__device__ float d_wh[14 * 7 * 64];                                 // conv1 fp32 [ci][kw][o]
__device__ float d_wm[8 * 64 * 9 * 64];                             // mid fp32 [L][(c*9+tap)*64+o]
__device__ __align__(16) uint32_t d_wf[8 * 9 * 4 * 8 * 128];        // B frags [L*9+tap][ks][n8][lane][4]
__device__ float d_wl[578];                                         // last conv fp32
__device__ float d_ct[512], d_st[512], d_win[512];                  // stft tables

// ======================= small PTX helpers =======================
__device__ __forceinline__ uint32_t smem_u32(const void* p) {
    uint32_t a;
    asm("{ .reg .u64 t; cvta.to.shared.u64 t, %1; cvt.u32.u64 %0, t; }" : "=r"(a) : "l"(p));
    return a;
}
__device__ __forceinline__ void cp16(uint32_t dst, const void* src, int src_bytes) {
    asm volatile("cp.async.cg.shared.global [%0], [%1], 16, %2;"
                 :: "r"(dst), "l"(src), "r"(src_bytes) : "memory");
}
#define CP_COMMIT() asm volatile("cp.async.commit_group;" ::: "memory")
#define CP_WAIT(n)  asm volatile("cp.async.wait_group %0;" :: "n"(n) : "memory")

__device__ __forceinline__ void hmma(float* c, const uint32_t* a, const uint32_t* b) {
    asm volatile(
        "mma.sync.aligned.m16n8k16.row.col.f32.bf16.bf16.f32 "
        "{%0,%1,%2,%3}, {%4,%5,%6,%7}, {%8,%9}, {%0,%1,%2,%3};"
        : "+f"(c[0]), "+f"(c[1]), "+f"(c[2]), "+f"(c[3])
        : "r"(a[0]), "r"(a[1]), "r"(a[2]), "r"(a[3]), "r"(b[0]), "r"(b[1]));
}
__device__ __forceinline__ void ldmx4(uint32_t* r, uint32_t addr) {
    asm volatile("ldmatrix.sync.aligned.m8n8.x4.shared.b16 {%0,%1,%2,%3}, [%4];"
        : "=r"(r[0]), "=r"(r[1]), "=r"(r[2]), "=r"(r[3]) : "r"(addr));
}
__device__ __forceinline__ void stmx4(uint32_t addr, const uint32_t* r) {
    asm volatile("stmatrix.sync.aligned.m8n8.x4.shared.b16 [%0], {%1,%2,%3,%4};"
        :: "r"(addr), "r"(r[0]), "r"(r[1]), "r"(r[2]), "r"(r[3]) : "memory");
}
__device__ __forceinline__ uint32_t pack_bf2(float a, float b) {
    __nv_bfloat162 h = __floats2bfloat162_rn(a, b);
    return *reinterpret_cast<uint32_t*>(&h);
}

// ======================= weight-norm prep (+ stft tables in bid 577) =======================
__global__ void prep_kernel(const float* __restrict__ v_h, const float* __restrict__ g_h,
                            const float* __restrict__ vs,  const float* __restrict__ gs,
                            const float* __restrict__ v_last, const float* __restrict__ g_last,
                            const float* __restrict__ b_last) {
    __shared__ float red[128];
    int bid = blockIdx.x, tid = threadIdx.x;

    if (bid == 577) {   // stft tables
        for (int i = tid; i < 512; i += 128) {
            d_win[i] = 0.5f - 0.5f * cospif(i * (1.0f / 256.0f));
            float ss, cc;
            sincospif(i * (1.0f / 256.0f), &ss, &cc);
            d_ct[i] = cc; d_st[i] = ss;
        }
        return;
    }

    const float* base; int n; float g; int o = 0;
    if (bid < 64)        { o = bid; base = v_h + o * 98; n = 98; g = g_h[o]; }
    else if (bid < 576)  { int L = (bid - 64) >> 6; o = (bid - 64) & 63;
                           base = vs + (size_t)(L * 64 + o) * 576; n = 576; g = gs[L * 64 + o]; }
    else                 { base = v_last; n = 576; g = g_last[0]; }

    float s = 0.f;
    for (int i = tid; i < n; i += 128) { float v = base[i]; s += v * v; }
    red[tid] = s; __syncthreads();
    for (int k = 64; k > 0; k >>= 1) { if (tid < k) red[tid] += red[tid + k]; __syncthreads(); }
    float scale = g * rsqrtf(red[0]);

    if (bid < 64) {
        for (int i = tid; i < n; i += 128) d_wh[i * 64 + o] = base[i] * scale;
    } else if (bid < 576) {
        int L = (bid - 64) >> 6;
        for (int i = tid; i < n; i += 128) d_wm[(size_t)L * 36864 + i * 64 + o] = base[i] * scale;
    } else {
        for (int i = tid; i < n; i += 128) d_wl[i] = base[i] * scale;
        if (tid == 0) d_wl[576] = b_last[0];
    }
}

// ======================= build B fragments: one uint4 per lane =======================
__global__ void wfrag_kernel() {
    int L = blockIdx.x, tap = blockIdx.y;
    const float* wm = d_wm + (size_t)L * 36864;
    for (int e = threadIdx.x; e < 1024; e += 256) {
        int lane = e & 31, n8 = (e >> 5) & 7, ks = e >> 8;
        int nn = n8 * 8 + (lane >> 2);
        uint32_t w[4];
        #pragma unroll
        for (int r = 0; r < 2; r++) {
            int k0 = ks * 16 + r * 8 + (lane & 3) * 2;
            float w0 = wm[(k0 * 9 + tap) * 64 + nn];
            float w1 = wm[((k0 + 1) * 9 + tap) * 64 + nn];
            __nv_bfloat16 h0 = __float2bfloat16(w0), h1 = __float2bfloat16(w1);
            __nv_bfloat16 l0 = __float2bfloat16(w0 - __bfloat162float(h0));
            __nv_bfloat16 l1 = __float2bfloat16(w1 - __bfloat162float(h1));
            w[r]     = ((uint32_t)__bfloat16_as_ushort(h1) << 16) | __bfloat16_as_ushort(h0);
            w[2 + r] = ((uint32_t)__bfloat16_as_ushort(l1) << 16) | __bfloat16_as_ushort(l0);
        }
        size_t idx = (((size_t)(L * 9 + tap) * 4 + ks) * 8 + n8) * 128 + lane * 4;
        *reinterpret_cast<uint4*>(d_wf + idx) = make_uint4(w[0], w[1], w[2], w[3]);
    }
}

// ======================= STFT (288 threads, precomputed tables) =======================
__global__ __launch_bounds__(288) void stft_kernel(const float* __restrict__ x) {
    __shared__ float s[512], ct[512], st[512];
    int t = blockIdx.x, b = blockIdx.y, tid = threadIdx.x;
    const float* xb = x + (size_t)b * 65536;
    for (int n = tid; n < 512; n += 288) {
        int idx = t * 256 + n - 256;
        if (idx < 0) idx = -idx;
        if (idx >= 65536) idx = 131070 - idx;
        s[n] = xb[idx] * d_win[n];
        ct[n] = d_ct[n]; st[n] = d_st[n];
    }
    __syncthreads();
    int f = tid;
    if (f < 257) {
        float re = 0.f, im = 0.f;
        int m = 0;
        #pragma unroll 8
        for (int n = 0; n < 512; n++) {
            float v = s[n];
            re += v * ct[m];
            im -= v * st[m];
            m = (m + f) & 511;
        }
        d_h[((size_t)(b * 2 + 0) * F_DIM + f) * T_DIM + t] = re;
        d_h[((size_t)(b * 2 + 1) * F_DIM + f) * T_DIM + t] = im;
    }
}

// ======================= fused lower + conv1 + leaky -> smem-staged coalesced stores =======================
__global__ __launch_bounds__(256) void conv1_kernel(const float* __restrict__ b_h) {
    __shared__ float sw[1792];
    __shared__ float sb[64];
    __shared__ __align__(16) unsigned char stage[2][128 * 144];   // hi, lo px rows (144B stride)
    int tid = threadIdx.x;
    for (int i = tid; i < 1792; i += 256) sw[i] = d_wh[4480 + i];
    if (tid < 64) sb[tid] = b_h[tid];
    __syncthreads();

    int half = tid >> 7, px = tid & 127;
    int pid = blockIdx.x * 128 + px;

    if (pid < NTOT) {
        int b = pid / NPIX, rem = pid % NPIX;
        int f = rem / T_DIM, t = rem % T_DIM;

        const float shift5 = 154.15067982725832f;   // 1000*ln(7/6)
        float src  = (float)f - shift5;
        float lof  = floorf(src);
        float frac = src - lof;
        int   il   = (int)lof;
        const float* hb0 = d_h + ((size_t)(b * 2 + 0) * F_DIM) * T_DIM;
        const float* hb1 = d_h + ((size_t)(b * 2 + 1) * F_DIM) * T_DIM;

        float low[4][7];
        #pragma unroll
        for (int kw = 0; kw < 7; kw++) {
            int tt = t + kw - 3;
            bool tv = (tt >= 0) && (tt < T_DIM);
            float a0 = 0.f, a1 = 0.f, c0 = 0.f, c1 = 0.f, i0 = 0.f, i1 = 0.f;
            if (tv) {
                if (il >= 0 && il < F_DIM)          { a0 = hb0[il * T_DIM + tt];        a1 = hb1[il * T_DIM + tt]; }
                if (il + 1 >= 0 && il + 1 < F_DIM)  { c0 = hb0[(il + 1) * T_DIM + tt];  c1 = hb1[(il + 1) * T_DIM + tt]; }
                i0 = hb0[f * T_DIM + tt]; i1 = hb1[f * T_DIM + tt];
            }
            low[0][kw] = (1.0f - frac) * a0 + frac * c0;
            low[1][kw] = (1.0f - frac) * a1 + frac * c1;
            low[2][kw] = i0;
            low[3][kw] = i1;
        }

        float acc[32];
        #pragma unroll
        for (int o = 0; o < 32; o++) acc[o] = sb[half * 32 + o];
        #pragma unroll
        for (int ci = 0; ci < 4; ci++) {
            #pragma unroll
            for (int kw = 0; kw < 7; kw++) {
                float xv = low[ci][kw];
                const float* wp = &sw[(ci * 7 + kw) * 64 + half * 32];
                #pragma unroll
                for (int o = 0; o < 32; o++) acc[o] += xv * wp[o];
            }
        }

        unsigned char* sh = stage[0] + px * 144 + half * 64;
        unsigned char* sl = stage[1] + px * 144 + half * 64;
        #pragma unroll
        for (int c8 = 0; c8 < 4; c8++) {
            float yv[8], hv[8];
            #pragma unroll
            for (int j = 0; j < 8; j++) {
                float y = acc[c8 * 8 + j];
                y = (y > 0.f) ? y : SLOPE * y;
                yv[j] = y;
                hv[j] = __bfloat162float(__float2bfloat16(y));
            }
            uint4 qh, ql;
            qh.x = pack_bf2(hv[0], hv[1]); qh.y = pack_bf2(hv[2], hv[3]);
            qh.z = pack_bf2(hv[4], hv[5]); qh.w = pack_bf2(hv[6], hv[7]);
            ql.x = pack_bf2(yv[0] - hv[0], yv[1] - hv[1]); ql.y = pack_bf2(yv[2] - hv[2], yv[3] - hv[3]);
            ql.z = pack_bf2(yv[4] - hv[4], yv[5] - hv[5]); ql.w = pack_bf2(yv[6] - hv[6], yv[7] - hv[7]);
            *reinterpret_cast<uint4*>(sh + c8 * 16) = qh;
            *reinterpret_cast<uint4*>(sl + c8 * 16) = ql;
        }
    }
    __syncthreads();

    // coalesced writeout: 2 arrays x 128 px x 8 chunks of 16B
    size_t pid0 = (size_t)blockIdx.x * 128;
    #pragma unroll
    for (int i0 = 0; i0 < 2048; i0 += 256) {
        int i = i0 + tid;
        int arr = i >> 10, r2 = i & 1023, p = r2 >> 3, col = r2 & 7;
        if (pid0 + p < NTOT) {
            uint4 v = *reinterpret_cast<const uint4*>(stage[arr] + p * 144 + col * 16);
            unsigned short* outp = arr ? d_a0l : d_a0h;
            *reinterpret_cast<uint4*>(outp + (pid0 + p) * 64 + col * 8) = v;
        }
    }
}

// ======================= dilated 3x3 conv: templated D + LAST fp32 finale =======================
#define AT_STRIDE 144
#define STAGE_BYTES (192 * AT_STRIDE)          // 4 pf rows x 48 t-slots
#define SM_BIAS_OFF (4 * STAGE_BYTES)          // 110592
#define CONV3_SMEM (SM_BIAS_OFF + 256)

template <int D, bool LAST>
__global__ __launch_bounds__(256, 2) void conv3_mma(int layer, const float* __restrict__ bs) {
    extern __shared__ __align__(16) unsigned char smem[];
    uint32_t sb = smem_u32(smem);
    int tid = threadIdx.x, wid = tid >> 5, lid = tid & 31;
    int t0 = blockIdx.x * 32, f0 = blockIdx.y * 4, b = blockIdx.z;
    constexpr int HW  = 32 + 2 * D;
    constexpr int HW8 = HW * 8;
    constexpr int E   = 4 * HW8;

    const unsigned short* inH = (layer & 1) ? d_a1h : d_a0h;
    const unsigned short* inL = (layer & 1) ? d_a1l : d_a0l;
    unsigned short* outH = (layer & 1) ? d_a0h : d_a1h;
    unsigned short* outL = (layer & 1) ? d_a0l : d_a1l;

    if (tid < 64) *reinterpret_cast<float*>(smem + SM_BIAS_OFF + tid * 4) = bs[layer * 64 + tid];

    int mrow0 = (wid & 3) * 32;
    int ocw   = (wid >> 2) * 32;
    int n8b   = (wid >> 2) * 4;

    int mat = lid >> 3, rowin = lid & 7;
    uint32_t laneoff = (uint32_t)(((mat & 1) * 8 + rowin) * AT_STRIDE + (mat >> 1) * 16);
    uint32_t pfoff   = (uint32_t)((mrow0 >> 5) * 48 * AT_STRIDE);

    float acc[2][4][4];
    #pragma unroll
    for (int m = 0; m < 2; m++)
        #pragma unroll
        for (int n = 0; n < 4; n++)
            #pragma unroll
            for (int r = 0; r < 4; r++) acc[m][n][r] = 0.f;

    // ---- prologue: burst-load group 0 (df = -D) into stage 0 ----
    {
        uint32_t baseH = sb, baseL = sb + STAGE_BYTES;
        #pragma unroll
        for (int e0 = 0; e0 < E; e0 += 256) {
            int e = e0 + tid;
            if (e < E) {
                int pf = e / HW8;
                int r = e - pf * HW8;
                int tl = r >> 3, cb = (r & 7) * 16;
                int gf = f0 + pf - D, gt = t0 - D + tl;
                bool ok = ((unsigned)gf < F_DIM) && ((unsigned)gt < T_DIM);
                size_t ridx = ok ? ((((size_t)b * F_DIM + gf) * T_DIM + gt) * 64) : 0;
                uint32_t off = (uint32_t)(pf * 48 + tl) * AT_STRIDE + cb;
                cp16(baseH + off, (const unsigned char*)inH + ridx * 2 + cb, ok ? 16 : 0);
                cp16(baseL + off, (const unsigned char*)inL + ridx * 2 + cb, ok ? 16 : 0);
            }
        }
        CP_COMMIT();
    }

    // ---- prime B-frag prefetch: tap 0, ks 0 ----
    const uint4* wfbase = reinterpret_cast<const uint4*>(d_wf) + (size_t)(layer * 9) * 1024;
    uint4 qbuf[4];
    #pragma unroll
    for (int n = 0; n < 4; n++)
        qbuf[n] = __ldg(&wfbase[(n8b + n) * 32 + lid]);

    #pragma unroll
    for (int g = 0; g < 3; g++) {
        CP_WAIT(0);
        __syncthreads();

        uint32_t aH = sb + (uint32_t)(g & 1) * 2u * STAGE_BYTES;
        uint32_t aL = aH + STAGE_BYTES;
        uint32_t nH = sb + (uint32_t)((g + 1) & 1) * 2u * STAGE_BYTES;
        uint32_t nL = nH + STAGE_BYTES;
        const int dfn = g * D;

        #pragma unroll
        for (int kt = 0; kt < 3; kt++) {
            int tap = g * 3 + kt;
            const uint4* wb = wfbase + (size_t)tap * 1024;
            uint32_t abase = pfoff + (uint32_t)(kt * D) * AT_STRIDE + laneoff;

            #pragma unroll
            for (int ks = 0; ks < 4; ks++) {
                uint32_t bh[4][2], bl[4][2];
                #pragma unroll
                for (int n = 0; n < 4; n++) {
                    bh[n][0] = qbuf[n].x; bh[n][1] = qbuf[n].y;
                    bl[n][0] = qbuf[n].z; bl[n][1] = qbuf[n].w;
                }
                if (!((g == 2) && (kt == 2) && (ks == 3))) {
                    const uint4* wbn = (ks < 3) ? wb : (wb + 1024);
                    int ksn = (ks < 3) ? (ks + 1) : 0;
                    #pragma unroll
                    for (int n = 0; n < 4; n++)
                        qbuf[n] = __ldg(&wbn[(ksn * 8 + n8b + n) * 32 + lid]);
                }

                uint32_t ah[2][4], al[2][4];
                ldmx4(ah[0], aH + abase + ks * 32);
                ldmx4(ah[1], aH + abase + 16 * AT_STRIDE + ks * 32);
                ldmx4(al[0], aL + abase + ks * 32);
                ldmx4(al[1], aL + abase + 16 * AT_STRIDE + ks * 32);

                #pragma unroll
                for (int m = 0; m < 2; m++)
                    #pragma unroll
                    for (int n = 0; n < 4; n++) hmma(acc[m][n], ah[m], bh[n]);
                #pragma unroll
                for (int m = 0; m < 2; m++)
                    #pragma unroll
                    for (int n = 0; n < 4; n++) hmma(acc[m][n], ah[m], bl[n]);
                #pragma unroll
                for (int m = 0; m < 2; m++)
                    #pragma unroll
                    for (int n = 0; n < 4; n++) hmma(acc[m][n], al[m], bh[n]);

                // interleaved chunk of next group's loads; single commit per group
                if (g < 2) {
                    int e = (kt * 4 + ks) * 256 + tid;
                    if (e < E) {
                        int pf = e / HW8;
                        int r = e - pf * HW8;
                        int tl = r >> 3, cb = (r & 7) * 16;
                        int gf = f0 + pf + dfn, gt = t0 - D + tl;
                        bool ok = ((unsigned)gf < F_DIM) && ((unsigned)gt < T_DIM);
                        size_t ridx = ok ? ((((size_t)b * F_DIM + gf) * T_DIM + gt) * 64) : 0;
                        uint32_t off = (uint32_t)(pf * 48 + tl) * AT_STRIDE + cb;
                        cp16(nH + off, (const unsigned char*)inH + ridx * 2 + cb, ok ? 16 : 0);
                        cp16(nL + off, (const unsigned char*)inL + ridx * 2 + cb, ok ? 16 : 0);
                    }
                }
            }
        }
        if (g < 2) CP_COMMIT();
    }
    __syncthreads();

    const float* bias = reinterpret_cast<const float*>(smem + SM_BIAS_OFF);

    if (LAST) {
        // ---- finale: stage fp32 rows in smem (272B stride), then coalesced writeout ----
        float* fst = reinterpret_cast<float*>(smem);
        #pragma unroll
        for (int m = 0; m < 2; m++) {
            #pragma unroll
            for (int r2 = 0; r2 < 2; r2++) {
                int p = mrow0 + m * 16 + (lid >> 2) + r2 * 8;
                #pragma unroll
                for (int n = 0; n < 4; n++) {
                    int oc = ocw + n * 8 + (lid & 3) * 2;
                    float y0 = acc[m][n][r2 * 2 + 0] + bias[oc];
                    float y1 = acc[m][n][r2 * 2 + 1] + bias[oc + 1];
                    y0 = (y0 > 0.f) ? y0 : SLOPE * y0;
                    y1 = (y1 > 0.f) ? y1 : SLOPE * y1;
                    *reinterpret_cast<float2*>(fst + p * 68 + oc) = make_float2(y0, y1);
                }
            }
        }
        __syncthreads();
        // writeout: 128 px x 16 chunks of 16B
        #pragma unroll
        for (int i0 = 0; i0 < 2048; i0 += 256) {
            int i = i0 + tid;
            int p = i >> 4, col = i & 15;
            int gf = f0 + (p >> 5), gt = t0 + (p & 31);
            if (gf < F_DIM && gt < T_DIM) {
                float4 v = *reinterpret_cast<const float4*>(fst + p * 68 + col * 4);
                size_t ridx = (((size_t)b * F_DIM + gf) * T_DIM + gt) * 64 + col * 4;
                *reinterpret_cast<float4*>(d_afin + ridx) = v;
            }
        }
    } else {
        // ---- epilogue: bias + leaky + hi/lo split, stmatrix staging, coalesced STG.128 ----
        uint32_t stg = sb + (uint32_t)wid * 5120u;
        unsigned char* stgp = smem + wid * 5120;

        #pragma unroll
        for (int m = 0; m < 2; m++) {
            uint32_t hreg[2][4], lreg[2][4];
            #pragma unroll
            for (int n = 0; n < 4; n++) {
                int oc = ocw + n * 8 + (lid & 3) * 2;
                float b0 = bias[oc], b1 = bias[oc + 1];
                #pragma unroll
                for (int r2 = 0; r2 < 2; r2++) {
                    float y0 = acc[m][n][r2 * 2 + 0] + b0;
                    float y1 = acc[m][n][r2 * 2 + 1] + b1;
                    y0 = (y0 > 0.f) ? y0 : SLOPE * y0;
                    y1 = (y1 > 0.f) ? y1 : SLOPE * y1;
                    float h0 = __bfloat162float(__float2bfloat16(y0));
                    float h1 = __bfloat162float(__float2bfloat16(y1));
                    hreg[r2][n] = pack_bf2(h0, h1);
                    lreg[r2][n] = pack_bf2(y0 - h0, y1 - h1);
                }
            }
            uint32_t arow = stg + (uint32_t)((m * 16 + rowin) * 80 + mat * 16);
            stmx4(arow,                 hreg[0]);
            stmx4(arow + 8 * 80,        hreg[1]);
            stmx4(arow + 2560,          lreg[0]);
            stmx4(arow + 2560 + 8 * 80, lreg[1]);
        }
        __syncwarp();

        int gfx = f0 + (wid & 3);
        if (gfx < F_DIM) {
            #pragma unroll
            for (int it = 0; it < 4; it++) {
                int p = it * 8 + (lid >> 2);
                int gt = t0 + p;
                uint4 vh = *reinterpret_cast<const uint4*>(stgp + p * 80 + (lid & 3) * 16);
                uint4 vl = *reinterpret_cast<const uint4*>(stgp + 2560 + p * 80 + (lid & 3) * 16);
                if (gt < T_DIM) {
                    size_t ridx = (((size_t)b * F_DIM + gfx) * T_DIM + gt) * 64 + ocw + (lid & 3) * 8;
                    *reinterpret_cast<uint4*>(outH + ridx) = vh;
                    *reinterpret_cast<uint4*>(outL + ridx) = vl;
                }
            }
        }
    }
}

// ======================= last conv (64 -> 1, 3x3, pad 1): fp32 smem-tiled =======================
#define L2_STRIDE 272                     // 256B px row + 16B pad (conflict-free LDS.128 phases)
#define L2_PX 340                         // 10 f x 34 t halo pixels
#define L2_SW (L2_PX * L2_STRIDE)         // 92480
#define L2_SMEM (L2_SW + 2320)

__global__ __launch_bounds__(256, 2) void last_kernel(float* __restrict__ out) {
    extern __shared__ __align__(16) unsigned char lsm[];
    uint32_t sbx = smem_u32(lsm);
    float* sw = reinterpret_cast<float*>(lsm + L2_SW);
    int tid = threadIdx.x;
    int t0 = blockIdx.x * 32, f0 = blockIdx.y * 8, b = blockIdx.z;

    for (int i = tid; i < 577; i += 256) sw[i] = d_wl[i];

    for (int e = tid; e < L2_PX * 16; e += 256) {
        int p = e >> 4, cb = (e & 15) * 16;
        int fl = p / 34, tl = p - fl * 34;
        int gf = f0 - 1 + fl, gt = t0 - 1 + tl;
        bool ok = ((unsigned)gf < F_DIM) && ((unsigned)gt < T_DIM);
        size_t ridx = ok ? ((((size_t)b * F_DIM + gf) * T_DIM + gt) * 64) : 0;
        cp16(sbx + p * L2_STRIDE + cb, (const unsigned char*)d_afin + ridx * 4 + cb, ok ? 16 : 0);
    }
    CP_COMMIT(); CP_WAIT(0);
    __syncthreads();

    int fl = tid >> 5, tl = tid & 31;
    int f = f0 + fl, t = t0 + tl;
    if (f >= F_DIM || t >= T_DIM) return;

    float acc = sw[576];
    #pragma unroll
    for (int kf = 0; kf < 3; kf++) {
        #pragma unroll
        for (int kt = 0; kt < 3; kt++) {
            int p = (fl + kf) * 34 + (tl + kt);
            const float4* px = reinterpret_cast<const float4*>(lsm + p * L2_STRIDE);
            int wi = kf * 3 + kt;
            #pragma unroll
            for (int c4 = 0; c4 < 16; c4++) {
                float4 v = px[c4];
                int c = c4 * 4;
                acc += v.x * sw[c * 9 + wi];
                acc += v.y * sw[(c + 1) * 9 + wi];
                acc += v.z * sw[(c + 2) * 9 + wi];
                acc += v.w * sw[(c + 3) * 9 + wi];
            }
        }
    }
    out[(size_t)b * NPIX + (size_t)f * T_DIM + t] = acc;
}

// ======================= launch =======================
extern "C" void kernel_launch(void* const* d_in, const int* in_sizes, int n_in,
                              void* d_out, int out_size) {
    const float* x      = (const float*)d_in[0];
    const float* v_h    = (const float*)d_in[1];
    const float* g_h    = (const float*)d_in[2];
    const float* b_h    = (const float*)d_in[3];
    const float* vs     = (const float*)d_in[4];
    const float* gs     = (const float*)d_in[5];
    const float* bs     = (const float*)d_in[6];
    const float* v_last = (const float*)d_in[7];
    const float* g_last = (const float*)d_in[8];
    const float* b_last = (const float*)d_in[9];
    float* out = (float*)d_out;

    cudaFuncSetAttribute(conv3_mma<1, false>, cudaFuncAttributeMaxDynamicSharedMemorySize, CONV3_SMEM);
    cudaFuncSetAttribute(conv3_mma<2, false>, cudaFuncAttributeMaxDynamicSharedMemorySize, CONV3_SMEM);
    cudaFuncSetAttribute(conv3_mma<3, false>, cudaFuncAttributeMaxDynamicSharedMemorySize, CONV3_SMEM);
    cudaFuncSetAttribute(conv3_mma<4, false>, cudaFuncAttributeMaxDynamicSharedMemorySize, CONV3_SMEM);
    cudaFuncSetAttribute(conv3_mma<5, false>, cudaFuncAttributeMaxDynamicSharedMemorySize, CONV3_SMEM);
    cudaFuncSetAttribute(conv3_mma<6, false>, cudaFuncAttributeMaxDynamicSharedMemorySize, CONV3_SMEM);
    cudaFuncSetAttribute(conv3_mma<7, false>, cudaFuncAttributeMaxDynamicSharedMemorySize, CONV3_SMEM);
    cudaFuncSetAttribute(conv3_mma<8, true>,  cudaFuncAttributeMaxDynamicSharedMemorySize, CONV3_SMEM);
    cudaFuncSetAttribute(last_kernel, cudaFuncAttributeMaxDynamicSharedMemorySize, L2_SMEM);

    prep_kernel<<<578, 128>>>(v_h, g_h, vs, gs, v_last, g_last, b_last);
    wfrag_kernel<<<dim3(8, 9), 256>>>();
    stft_kernel<<<dim3(257, NB), 288>>>(x);
    conv1_kernel<<<(NTOT + 127) / 128, 256>>>(b_h);

    dim3 cg(9, 65, NB);
    conv3_mma<1, false><<<cg, 256, CONV3_SMEM>>>(0, bs);
    conv3_mma<2, false><<<cg, 256, CONV3_SMEM>>>(1, bs);
    conv3_mma<3, false><<<cg, 256, CONV3_SMEM>>>(2, bs);
    conv3_mma<4, false><<<cg, 256, CONV3_SMEM>>>(3, bs);
    conv3_mma<5, false><<<cg, 256, CONV3_SMEM>>>(4, bs);
    conv3_mma<6, false><<<cg, 256, CONV3_SMEM>>>(5, bs);
    conv3_mma<7, false><<<cg, 256, CONV3_SMEM>>>(6, bs);
    conv3_mma<8, true><<<cg, 256, CONV3_SMEM>>>(7, bs);

    last_kernel<<<dim3(9, 33, NB), 256, L2_SMEM>>>(out);
}

// round 15
// speedup vs baseline: 1.0323x; 1.0323x over previous
#include <cuda_runtime.h>
#include <cuda_bf16.h>
#include <stdint.h>
#include <math.h>

#define F_DIM 257
#define T_DIM 257
#define NB 4
#define NPIX (F_DIM * T_DIM)        // 66049
#define NTOT (NB * NPIX)            // 264196
#define SLOPE 0.2f

// ======================= scratch =======================
__device__ float d_h[NB * 2 * NPIX];                                // STFT (B,2,F,T)
__device__ __align__(16) unsigned short d_a0h[(size_t)NTOT * 64];   // NHWC bf16 hi
__device__ __align__(16) unsigned short d_a0l[(size_t)NTOT * 64];   // NHWC bf16 lo
__device__ __align__(16) unsigned short d_a1h[(size_t)NTOT * 64];
__device__ __align__(16) unsigned short d_a1l[(size_t)NTOT * 64];
__device__ __align__(16) float d_afin[(size_t)NTOT * 64];           // final conv3 out, fp32 NHWC
__device__ float d_wh[14 * 7 * 64];                                 // conv1 fp32 [ci][kw][o]
__device__ float d_wm[8 * 64 * 9 * 64];                             // mid fp32 [L][(c*9+tap)*64+o]
__device__ __align__(16) uint32_t d_wf[8 * 9 * 4 * 8 * 128];        // B frags [L*9+tap][ks][n8][lane][4]
__device__ float d_wl[578];                                         // last conv fp32
__device__ float d_win[512];                                        // stft window
__device__ __align__(8) float2 d_tw[256];                           // (cos,sin) 2πk/256
__device__ __align__(8) float2 d_cw[256];                           // (cos,sin) πf/256 combine

// ======================= small PTX helpers =======================
__device__ __forceinline__ uint32_t smem_u32(const void* p) {
    uint32_t a;
    asm("{ .reg .u64 t; cvta.to.shared.u64 t, %1; cvt.u32.u64 %0, t; }" : "=r"(a) : "l"(p));
    return a;
}
__device__ __forceinline__ void cp16(uint32_t dst, const void* src, int src_bytes) {
    asm volatile("cp.async.cg.shared.global [%0], [%1], 16, %2;"
                 :: "r"(dst), "l"(src), "r"(src_bytes) : "memory");
}
#define CP_COMMIT() asm volatile("cp.async.commit_group;" ::: "memory")
#define CP_WAIT(n)  asm volatile("cp.async.wait_group %0;" :: "n"(n) : "memory")

__device__ __forceinline__ void hmma(float* c, const uint32_t* a, const uint32_t* b) {
    asm volatile(
        "mma.sync.aligned.m16n8k16.row.col.f32.bf16.bf16.f32 "
        "{%0,%1,%2,%3}, {%4,%5,%6,%7}, {%8,%9}, {%0,%1,%2,%3};"
        : "+f"(c[0]), "+f"(c[1]), "+f"(c[2]), "+f"(c[3])
        : "r"(a[0]), "r"(a[1]), "r"(a[2]), "r"(a[3]), "r"(b[0]), "r"(b[1]));
}
__device__ __forceinline__ void ldmx4(uint32_t* r, uint32_t addr) {
    asm volatile("ldmatrix.sync.aligned.m8n8.x4.shared.b16 {%0,%1,%2,%3}, [%4];"
        : "=r"(r[0]), "=r"(r[1]), "=r"(r[2]), "=r"(r[3]) : "r"(addr));
}
__device__ __forceinline__ void stmx4(uint32_t addr, const uint32_t* r) {
    asm volatile("stmatrix.sync.aligned.m8n8.x4.shared.b16 [%0], {%1,%2,%3,%4};"
        :: "r"(addr), "r"(r[0]), "r"(r[1]), "r"(r[2]), "r"(r[3]) : "memory");
}
__device__ __forceinline__ uint32_t pack_bf2(float a, float b) {
    __nv_bfloat162 h = __floats2bfloat162_rn(a, b);
    return *reinterpret_cast<uint32_t*>(&h);
}

// ======================= weight-norm prep (+ stft tables in bid 577) =======================
__global__ void prep_kernel(const float* __restrict__ v_h, const float* __restrict__ g_h,
                            const float* __restrict__ vs,  const float* __restrict__ gs,
                            const float* __restrict__ v_last, const float* __restrict__ g_last,
                            const float* __restrict__ b_last) {
    __shared__ float red[128];
    int bid = blockIdx.x, tid = threadIdx.x;

    if (bid == 577) {   // stft tables
        for (int i = tid; i < 512; i += 128)
            d_win[i] = 0.5f - 0.5f * cospif(i * (1.0f / 256.0f));
        for (int i = tid; i < 256; i += 128) {
            float ss, cc;
            sincospif(i * (1.0f / 128.0f), &ss, &cc);   // 2πi/256
            d_tw[i] = make_float2(cc, ss);
            sincospif(i * (1.0f / 256.0f), &ss, &cc);   // πi/256
            d_cw[i] = make_float2(cc, ss);
        }
        return;
    }

    const float* base; int n; float g; int o = 0;
    if (bid < 64)        { o = bid; base = v_h + o * 98; n = 98; g = g_h[o]; }
    else if (bid < 576)  { int L = (bid - 64) >> 6; o = (bid - 64) & 63;
                           base = vs + (size_t)(L * 64 + o) * 576; n = 576; g = gs[L * 64 + o]; }
    else                 { base = v_last; n = 576; g = g_last[0]; }

    float s = 0.f;
    for (int i = tid; i < n; i += 128) { float v = base[i]; s += v * v; }
    red[tid] = s; __syncthreads();
    for (int k = 64; k > 0; k >>= 1) { if (tid < k) red[tid] += red[tid + k]; __syncthreads(); }
    float scale = g * rsqrtf(red[0]);

    if (bid < 64) {
        for (int i = tid; i < n; i += 128) d_wh[i * 64 + o] = base[i] * scale;
    } else if (bid < 576) {
        int L = (bid - 64) >> 6;
        for (int i = tid; i < n; i += 128) d_wm[(size_t)L * 36864 + i * 64 + o] = base[i] * scale;
    } else {
        for (int i = tid; i < n; i += 128) d_wl[i] = base[i] * scale;
        if (tid == 0) d_wl[576] = b_last[0];
    }
}

// ======================= build B fragments: one uint4 per lane =======================
__global__ void wfrag_kernel() {
    int L = blockIdx.x, tap = blockIdx.y;
    const float* wm = d_wm + (size_t)L * 36864;
    for (int e = threadIdx.x; e < 1024; e += 256) {
        int lane = e & 31, n8 = (e >> 5) & 7, ks = e >> 8;
        int nn = n8 * 8 + (lane >> 2);
        uint32_t w[4];
        #pragma unroll
        for (int r = 0; r < 2; r++) {
            int k0 = ks * 16 + r * 8 + (lane & 3) * 2;
            float w0 = wm[(k0 * 9 + tap) * 64 + nn];
            float w1 = wm[((k0 + 1) * 9 + tap) * 64 + nn];
            __nv_bfloat16 h0 = __float2bfloat16(w0), h1 = __float2bfloat16(w1);
            __nv_bfloat16 l0 = __float2bfloat16(w0 - __bfloat162float(h0));
            __nv_bfloat16 l1 = __float2bfloat16(w1 - __bfloat162float(h1));
            w[r]     = ((uint32_t)__bfloat16_as_ushort(h1) << 16) | __bfloat16_as_ushort(h0);
            w[2 + r] = ((uint32_t)__bfloat16_as_ushort(l1) << 16) | __bfloat16_as_ushort(l0);
        }
        size_t idx = (((size_t)(L * 9 + tap) * 4 + ks) * 8 + n8) * 128 + lane * 4;
        *reinterpret_cast<uint4*>(d_wf + idx) = make_uint4(w[0], w[1], w[2], w[3]);
    }
}

// ======================= STFT: one radix-2 DIT level, 256 threads =======================
__global__ __launch_bounds__(256) void stft_kernel(const float* __restrict__ x) {
    __shared__ float2 seo[256];    // (even, odd) windowed samples
    __shared__ float2 tw[256];     // (cos, sin) 2πk/256
    int t = blockIdx.x, b = blockIdx.y, tid = threadIdx.x;
    const float* xb = x + (size_t)b * 65536;

    {
        int n0 = tid * 2, n1 = n0 + 1;
        int i0 = t * 256 + n0 - 256;
        int i1 = i0 + 1;
        if (i0 < 0) i0 = -i0;
        if (i0 >= 65536) i0 = 131070 - i0;
        if (i1 < 0) i1 = -i1;
        if (i1 >= 65536) i1 = 131070 - i1;
        seo[tid] = make_float2(xb[i0] * d_win[n0], xb[i1] * d_win[n1]);
        tw[tid] = d_tw[tid];
    }
    __syncthreads();

    int f = tid;    // 0..255
    float eR = 0.f, eI = 0.f, oR = 0.f, oI = 0.f;
    int m = 0;
    #pragma unroll 8
    for (int k = 0; k < 256; k++) {
        float2 v = seo[k];
        float2 w = tw[m];
        eR += v.x * w.x;
        eI -= v.x * w.y;
        oR += v.y * w.x;
        oI -= v.y * w.y;
        m = (m + f) & 255;
    }
    // combine: X(f) = E(f) + e^{-iπf/256} O(f)
    float2 cw = d_cw[f];
    float re = eR + (cw.x * oR + cw.y * oI);
    float im = eI + (cw.x * oI - cw.y * oR);
    d_h[((size_t)(b * 2 + 0) * F_DIM + f) * T_DIM + t] = re;
    d_h[((size_t)(b * 2 + 1) * F_DIM + f) * T_DIM + t] = im;
    if (f == 0) {   // X(256) = ΣE − ΣO, imag exactly 0
        d_h[((size_t)(b * 2 + 0) * F_DIM + 256) * T_DIM + t] = eR - oR;
        d_h[((size_t)(b * 2 + 1) * F_DIM + 256) * T_DIM + t] = 0.f;
    }
}

// ======================= fused lower + conv1 + leaky -> smem-staged coalesced stores =======================
__global__ __launch_bounds__(256) void conv1_kernel(const float* __restrict__ b_h) {
    __shared__ float sw[1792];
    __shared__ float sb[64];
    __shared__ __align__(16) unsigned char stage[2][128 * 144];   // hi, lo px rows (144B stride)
    int tid = threadIdx.x;
    for (int i = tid; i < 1792; i += 256) sw[i] = d_wh[4480 + i];
    if (tid < 64) sb[tid] = b_h[tid];
    __syncthreads();

    int half = tid >> 7, px = tid & 127;
    int pid = blockIdx.x * 128 + px;

    if (pid < NTOT) {
        int b = pid / NPIX, rem = pid % NPIX;
        int f = rem / T_DIM, t = rem % T_DIM;

        const float shift5 = 154.15067982725832f;   // 1000*ln(7/6)
        float src  = (float)f - shift5;
        float lof  = floorf(src);
        float frac = src - lof;
        int   il   = (int)lof;
        const float* hb0 = d_h + ((size_t)(b * 2 + 0) * F_DIM) * T_DIM;
        const float* hb1 = d_h + ((size_t)(b * 2 + 1) * F_DIM) * T_DIM;

        float low[4][7];
        #pragma unroll
        for (int kw = 0; kw < 7; kw++) {
            int tt = t + kw - 3;
            bool tv = (tt >= 0) && (tt < T_DIM);
            float a0 = 0.f, a1 = 0.f, c0 = 0.f, c1 = 0.f, i0 = 0.f, i1 = 0.f;
            if (tv) {
                if (il >= 0 && il < F_DIM)          { a0 = hb0[il * T_DIM + tt];        a1 = hb1[il * T_DIM + tt]; }
                if (il + 1 >= 0 && il + 1 < F_DIM)  { c0 = hb0[(il + 1) * T_DIM + tt];  c1 = hb1[(il + 1) * T_DIM + tt]; }
                i0 = hb0[f * T_DIM + tt]; i1 = hb1[f * T_DIM + tt];
            }
            low[0][kw] = (1.0f - frac) * a0 + frac * c0;
            low[1][kw] = (1.0f - frac) * a1 + frac * c1;
            low[2][kw] = i0;
            low[3][kw] = i1;
        }

        float acc[32];
        #pragma unroll
        for (int o = 0; o < 32; o++) acc[o] = sb[half * 32 + o];
        #pragma unroll
        for (int ci = 0; ci < 4; ci++) {
            #pragma unroll
            for (int kw = 0; kw < 7; kw++) {
                float xv = low[ci][kw];
                const float* wp = &sw[(ci * 7 + kw) * 64 + half * 32];
                #pragma unroll
                for (int o = 0; o < 32; o++) acc[o] += xv * wp[o];
            }
        }

        unsigned char* sh = stage[0] + px * 144 + half * 64;
        unsigned char* sl = stage[1] + px * 144 + half * 64;
        #pragma unroll
        for (int c8 = 0; c8 < 4; c8++) {
            float yv[8], hv[8];
            #pragma unroll
            for (int j = 0; j < 8; j++) {
                float y = acc[c8 * 8 + j];
                y = (y > 0.f) ? y : SLOPE * y;
                yv[j] = y;
                hv[j] = __bfloat162float(__float2bfloat16(y));
            }
            uint4 qh, ql;
            qh.x = pack_bf2(hv[0], hv[1]); qh.y = pack_bf2(hv[2], hv[3]);
            qh.z = pack_bf2(hv[4], hv[5]); qh.w = pack_bf2(hv[6], hv[7]);
            ql.x = pack_bf2(yv[0] - hv[0], yv[1] - hv[1]); ql.y = pack_bf2(yv[2] - hv[2], yv[3] - hv[3]);
            ql.z = pack_bf2(yv[4] - hv[4], yv[5] - hv[5]); ql.w = pack_bf2(yv[6] - hv[6], yv[7] - hv[7]);
            *reinterpret_cast<uint4*>(sh + c8 * 16) = qh;
            *reinterpret_cast<uint4*>(sl + c8 * 16) = ql;
        }
    }
    __syncthreads();

    // coalesced writeout: 2 arrays x 128 px x 8 chunks of 16B
    size_t pid0 = (size_t)blockIdx.x * 128;
    #pragma unroll
    for (int i0 = 0; i0 < 2048; i0 += 256) {
        int i = i0 + tid;
        int arr = i >> 10, r2 = i & 1023, p = r2 >> 3, col = r2 & 7;
        if (pid0 + p < NTOT) {
            uint4 v = *reinterpret_cast<const uint4*>(stage[arr] + p * 144 + col * 16);
            unsigned short* outp = arr ? d_a0l : d_a0h;
            *reinterpret_cast<uint4*>(outp + (pid0 + p) * 64 + col * 8) = v;
        }
    }
}

// ======================= dilated 3x3 conv: templated D + LAST fp32 finale =======================
#define AT_STRIDE 144
#define STAGE_BYTES (192 * AT_STRIDE)          // 4 pf rows x 48 t-slots
#define SM_BIAS_OFF (4 * STAGE_BYTES)          // 110592
#define CONV3_SMEM (SM_BIAS_OFF + 256)

template <int D, bool LAST>
__global__ __launch_bounds__(256, 2) void conv3_mma(int layer, const float* __restrict__ bs) {
    extern __shared__ __align__(16) unsigned char smem[];
    uint32_t sb = smem_u32(smem);
    int tid = threadIdx.x, wid = tid >> 5, lid = tid & 31;
    int t0 = blockIdx.x * 32, f0 = blockIdx.y * 4, b = blockIdx.z;
    constexpr int HW  = 32 + 2 * D;
    constexpr int HW8 = HW * 8;
    constexpr int E   = 4 * HW8;

    const unsigned short* inH = (layer & 1) ? d_a1h : d_a0h;
    const unsigned short* inL = (layer & 1) ? d_a1l : d_a0l;
    unsigned short* outH = (layer & 1) ? d_a0h : d_a1h;
    unsigned short* outL = (layer & 1) ? d_a0l : d_a1l;

    if (tid < 64) *reinterpret_cast<float*>(smem + SM_BIAS_OFF + tid * 4) = bs[layer * 64 + tid];

    int mrow0 = (wid & 3) * 32;
    int ocw   = (wid >> 2) * 32;
    int n8b   = (wid >> 2) * 4;

    int mat = lid >> 3, rowin = lid & 7;
    uint32_t laneoff = (uint32_t)(((mat & 1) * 8 + rowin) * AT_STRIDE + (mat >> 1) * 16);
    uint32_t pfoff   = (uint32_t)((mrow0 >> 5) * 48 * AT_STRIDE);

    float acc[2][4][4];
    #pragma unroll
    for (int m = 0; m < 2; m++)
        #pragma unroll
        for (int n = 0; n < 4; n++)
            #pragma unroll
            for (int r = 0; r < 4; r++) acc[m][n][r] = 0.f;

    // ---- prologue: burst-load group 0 (df = -D) into stage 0 ----
    {
        uint32_t baseH = sb, baseL = sb + STAGE_BYTES;
        #pragma unroll
        for (int e0 = 0; e0 < E; e0 += 256) {
            int e = e0 + tid;
            if (e < E) {
                int pf = e / HW8;
                int r = e - pf * HW8;
                int tl = r >> 3, cb = (r & 7) * 16;
                int gf = f0 + pf - D, gt = t0 - D + tl;
                bool ok = ((unsigned)gf < F_DIM) && ((unsigned)gt < T_DIM);
                size_t ridx = ok ? ((((size_t)b * F_DIM + gf) * T_DIM + gt) * 64) : 0;
                uint32_t off = (uint32_t)(pf * 48 + tl) * AT_STRIDE + cb;
                cp16(baseH + off, (const unsigned char*)inH + ridx * 2 + cb, ok ? 16 : 0);
                cp16(baseL + off, (const unsigned char*)inL + ridx * 2 + cb, ok ? 16 : 0);
            }
        }
        CP_COMMIT();
    }

    // ---- prime B-frag prefetch: tap 0, ks 0 ----
    const uint4* wfbase = reinterpret_cast<const uint4*>(d_wf) + (size_t)(layer * 9) * 1024;
    uint4 qbuf[4];
    #pragma unroll
    for (int n = 0; n < 4; n++)
        qbuf[n] = __ldg(&wfbase[(n8b + n) * 32 + lid]);

    #pragma unroll
    for (int g = 0; g < 3; g++) {
        CP_WAIT(0);
        __syncthreads();

        uint32_t aH = sb + (uint32_t)(g & 1) * 2u * STAGE_BYTES;
        uint32_t aL = aH + STAGE_BYTES;
        uint32_t nH = sb + (uint32_t)((g + 1) & 1) * 2u * STAGE_BYTES;
        uint32_t nL = nH + STAGE_BYTES;
        const int dfn = g * D;

        #pragma unroll
        for (int kt = 0; kt < 3; kt++) {
            int tap = g * 3 + kt;
            const uint4* wb = wfbase + (size_t)tap * 1024;
            uint32_t abase = pfoff + (uint32_t)(kt * D) * AT_STRIDE + laneoff;

            #pragma unroll
            for (int ks = 0; ks < 4; ks++) {
                uint32_t bh[4][2], bl[4][2];
                #pragma unroll
                for (int n = 0; n < 4; n++) {
                    bh[n][0] = qbuf[n].x; bh[n][1] = qbuf[n].y;
                    bl[n][0] = qbuf[n].z; bl[n][1] = qbuf[n].w;
                }
                if (!((g == 2) && (kt == 2) && (ks == 3))) {
                    const uint4* wbn = (ks < 3) ? wb : (wb + 1024);
                    int ksn = (ks < 3) ? (ks + 1) : 0;
                    #pragma unroll
                    for (int n = 0; n < 4; n++)
                        qbuf[n] = __ldg(&wbn[(ksn * 8 + n8b + n) * 32 + lid]);
                }

                uint32_t ah[2][4], al[2][4];
                ldmx4(ah[0], aH + abase + ks * 32);
                ldmx4(ah[1], aH + abase + 16 * AT_STRIDE + ks * 32);
                ldmx4(al[0], aL + abase + ks * 32);
                ldmx4(al[1], aL + abase + 16 * AT_STRIDE + ks * 32);

                #pragma unroll
                for (int m = 0; m < 2; m++)
                    #pragma unroll
                    for (int n = 0; n < 4; n++) hmma(acc[m][n], ah[m], bh[n]);
                #pragma unroll
                for (int m = 0; m < 2; m++)
                    #pragma unroll
                    for (int n = 0; n < 4; n++) hmma(acc[m][n], ah[m], bl[n]);
                #pragma unroll
                for (int m = 0; m < 2; m++)
                    #pragma unroll
                    for (int n = 0; n < 4; n++) hmma(acc[m][n], al[m], bh[n]);

                // interleaved chunk of next group's loads; single commit per group
                if (g < 2) {
                    int e = (kt * 4 + ks) * 256 + tid;
                    if (e < E) {
                        int pf = e / HW8;
                        int r = e - pf * HW8;
                        int tl = r >> 3, cb = (r & 7) * 16;
                        int gf = f0 + pf + dfn, gt = t0 - D + tl;
                        bool ok = ((unsigned)gf < F_DIM) && ((unsigned)gt < T_DIM);
                        size_t ridx = ok ? ((((size_t)b * F_DIM + gf) * T_DIM + gt) * 64) : 0;
                        uint32_t off = (uint32_t)(pf * 48 + tl) * AT_STRIDE + cb;
                        cp16(nH + off, (const unsigned char*)inH + ridx * 2 + cb, ok ? 16 : 0);
                        cp16(nL + off, (const unsigned char*)inL + ridx * 2 + cb, ok ? 16 : 0);
                    }
                }
            }
        }
        if (g < 2) CP_COMMIT();
    }
    __syncthreads();

    const float* bias = reinterpret_cast<const float*>(smem + SM_BIAS_OFF);

    if (LAST) {
        // ---- finale: stage fp32 rows in smem (272B stride), then coalesced writeout ----
        float* fst = reinterpret_cast<float*>(smem);
        #pragma unroll
        for (int m = 0; m < 2; m++) {
            #pragma unroll
            for (int r2 = 0; r2 < 2; r2++) {
                int p = mrow0 + m * 16 + (lid >> 2) + r2 * 8;
                #pragma unroll
                for (int n = 0; n < 4; n++) {
                    int oc = ocw + n * 8 + (lid & 3) * 2;
                    float y0 = acc[m][n][r2 * 2 + 0] + bias[oc];
                    float y1 = acc[m][n][r2 * 2 + 1] + bias[oc + 1];
                    y0 = (y0 > 0.f) ? y0 : SLOPE * y0;
                    y1 = (y1 > 0.f) ? y1 : SLOPE * y1;
                    *reinterpret_cast<float2*>(fst + p * 68 + oc) = make_float2(y0, y1);
                }
            }
        }
        __syncthreads();
        // writeout: 128 px x 16 chunks of 16B
        #pragma unroll
        for (int i0 = 0; i0 < 2048; i0 += 256) {
            int i = i0 + tid;
            int p = i >> 4, col = i & 15;
            int gf = f0 + (p >> 5), gt = t0 + (p & 31);
            if (gf < F_DIM && gt < T_DIM) {
                float4 v = *reinterpret_cast<const float4*>(fst + p * 68 + col * 4);
                size_t ridx = (((size_t)b * F_DIM + gf) * T_DIM + gt) * 64 + col * 4;
                *reinterpret_cast<float4*>(d_afin + ridx) = v;
            }
        }
    } else {
        // ---- epilogue: bias + leaky + hi/lo split, stmatrix staging, coalesced STG.128 ----
        uint32_t stg = sb + (uint32_t)wid * 5120u;
        unsigned char* stgp = smem + wid * 5120;

        #pragma unroll
        for (int m = 0; m < 2; m++) {
            uint32_t hreg[2][4], lreg[2][4];
            #pragma unroll
            for (int n = 0; n < 4; n++) {
                int oc = ocw + n * 8 + (lid & 3) * 2;
                float b0 = bias[oc], b1 = bias[oc + 1];
                #pragma unroll
                for (int r2 = 0; r2 < 2; r2++) {
                    float y0 = acc[m][n][r2 * 2 + 0] + b0;
                    float y1 = acc[m][n][r2 * 2 + 1] + b1;
                    y0 = (y0 > 0.f) ? y0 : SLOPE * y0;
                    y1 = (y1 > 0.f) ? y1 : SLOPE * y1;
                    float h0 = __bfloat162float(__float2bfloat16(y0));
                    float h1 = __bfloat162float(__float2bfloat16(y1));
                    hreg[r2][n] = pack_bf2(h0, h1);
                    lreg[r2][n] = pack_bf2(y0 - h0, y1 - h1);
                }
            }
            uint32_t arow = stg + (uint32_t)((m * 16 + rowin) * 80 + mat * 16);
            stmx4(arow,                 hreg[0]);
            stmx4(arow + 8 * 80,        hreg[1]);
            stmx4(arow + 2560,          lreg[0]);
            stmx4(arow + 2560 + 8 * 80, lreg[1]);
        }
        __syncwarp();

        int gfx = f0 + (wid & 3);
        if (gfx < F_DIM) {
            #pragma unroll
            for (int it = 0; it < 4; it++) {
                int p = it * 8 + (lid >> 2);
                int gt = t0 + p;
                uint4 vh = *reinterpret_cast<const uint4*>(stgp + p * 80 + (lid & 3) * 16);
                uint4 vl = *reinterpret_cast<const uint4*>(stgp + 2560 + p * 80 + (lid & 3) * 16);
                if (gt < T_DIM) {
                    size_t ridx = (((size_t)b * F_DIM + gfx) * T_DIM + gt) * 64 + ocw + (lid & 3) * 8;
                    *reinterpret_cast<uint4*>(outH + ridx) = vh;
                    *reinterpret_cast<uint4*>(outL + ridx) = vl;
                }
            }
        }
    }
}

// ======================= last conv (64 -> 1, 3x3, pad 1): fp32 smem-tiled =======================
#define L2_STRIDE 272                     // 256B px row + 16B pad (conflict-free LDS.128 phases)
#define L2_PX 340                         // 10 f x 34 t halo pixels
#define L2_SW (L2_PX * L2_STRIDE)         // 92480
#define L2_SMEM (L2_SW + 2320)

__global__ __launch_bounds__(256, 2) void last_kernel(float* __restrict__ out) {
    extern __shared__ __align__(16) unsigned char lsm[];
    uint32_t sbx = smem_u32(lsm);
    float* sw = reinterpret_cast<float*>(lsm + L2_SW);
    int tid = threadIdx.x;
    int t0 = blockIdx.x * 32, f0 = blockIdx.y * 8, b = blockIdx.z;

    for (int i = tid; i < 577; i += 256) sw[i] = d_wl[i];

    for (int e = tid; e < L2_PX * 16; e += 256) {
        int p = e >> 4, cb = (e & 15) * 16;
        int fl = p / 34, tl = p - fl * 34;
        int gf = f0 - 1 + fl, gt = t0 - 1 + tl;
        bool ok = ((unsigned)gf < F_DIM) && ((unsigned)gt < T_DIM);
        size_t ridx = ok ? ((((size_t)b * F_DIM + gf) * T_DIM + gt) * 64) : 0;
        cp16(sbx + p * L2_STRIDE + cb, (const unsigned char*)d_afin + ridx * 4 + cb, ok ? 16 : 0);
    }
    CP_COMMIT(); CP_WAIT(0);
    __syncthreads();

    int fl = tid >> 5, tl = tid & 31;
    int f = f0 + fl, t = t0 + tl;
    if (f >= F_DIM || t >= T_DIM) return;

    float acc = sw[576];
    #pragma unroll
    for (int kf = 0; kf < 3; kf++) {
        #pragma unroll
        for (int kt = 0; kt < 3; kt++) {
            int p = (fl + kf) * 34 + (tl + kt);
            const float4* px = reinterpret_cast<const float4*>(lsm + p * L2_STRIDE);
            int wi = kf * 3 + kt;
            #pragma unroll
            for (int c4 = 0; c4 < 16; c4++) {
                float4 v = px[c4];
                int c = c4 * 4;
                acc += v.x * sw[c * 9 + wi];
                acc += v.y * sw[(c + 1) * 9 + wi];
                acc += v.z * sw[(c + 2) * 9 + wi];
                acc += v.w * sw[(c + 3) * 9 + wi];
            }
        }
    }
    out[(size_t)b * NPIX + (size_t)f * T_DIM + t] = acc;
}

// ======================= launch =======================
extern "C" void kernel_launch(void* const* d_in, const int* in_sizes, int n_in,
                              void* d_out, int out_size) {
    const float* x      = (const float*)d_in[0];
    const float* v_h    = (const float*)d_in[1];
    const float* g_h    = (const float*)d_in[2];
    const float* b_h    = (const float*)d_in[3];
    const float* vs     = (const float*)d_in[4];
    const float* gs     = (const float*)d_in[5];
    const float* bs     = (const float*)d_in[6];
    const float* v_last = (const float*)d_in[7];
    const float* g_last = (const float*)d_in[8];
    const float* b_last = (const float*)d_in[9];
    float* out = (float*)d_out;

    cudaFuncSetAttribute(conv3_mma<1, false>, cudaFuncAttributeMaxDynamicSharedMemorySize, CONV3_SMEM);
    cudaFuncSetAttribute(conv3_mma<2, false>, cudaFuncAttributeMaxDynamicSharedMemorySize, CONV3_SMEM);
    cudaFuncSetAttribute(conv3_mma<3, false>, cudaFuncAttributeMaxDynamicSharedMemorySize, CONV3_SMEM);
    cudaFuncSetAttribute(conv3_mma<4, false>, cudaFuncAttributeMaxDynamicSharedMemorySize, CONV3_SMEM);
    cudaFuncSetAttribute(conv3_mma<5, false>, cudaFuncAttributeMaxDynamicSharedMemorySize, CONV3_SMEM);
    cudaFuncSetAttribute(conv3_mma<6, false>, cudaFuncAttributeMaxDynamicSharedMemorySize, CONV3_SMEM);
    cudaFuncSetAttribute(conv3_mma<7, false>, cudaFuncAttributeMaxDynamicSharedMemorySize, CONV3_SMEM);
    cudaFuncSetAttribute(conv3_mma<8, true>,  cudaFuncAttributeMaxDynamicSharedMemorySize, CONV3_SMEM);
    cudaFuncSetAttribute(last_kernel, cudaFuncAttributeMaxDynamicSharedMemorySize, L2_SMEM);

    prep_kernel<<<578, 128>>>(v_h, g_h, vs, gs, v_last, g_last, b_last);
    wfrag_kernel<<<dim3(8, 9), 256>>>();
    stft_kernel<<<dim3(257, NB), 256>>>(x);
    conv1_kernel<<<(NTOT + 127) / 128, 256>>>(b_h);

    dim3 cg(9, 65, NB);
    conv3_mma<1, false><<<cg, 256, CONV3_SMEM>>>(0, bs);
    conv3_mma<2, false><<<cg, 256, CONV3_SMEM>>>(1, bs);
    conv3_mma<3, false><<<cg, 256, CONV3_SMEM>>>(2, bs);
    conv3_mma<4, false><<<cg, 256, CONV3_SMEM>>>(3, bs);
    conv3_mma<5, false><<<cg, 256, CONV3_SMEM>>>(4, bs);
    conv3_mma<6, false><<<cg, 256, CONV3_SMEM>>>(5, bs);
    conv3_mma<7, false><<<cg, 256, CONV3_SMEM>>>(6, bs);
    conv3_mma<8, true><<<cg, 256, CONV3_SMEM>>>(7, bs);

    last_kernel<<<dim3(9, 33, NB), 256, L2_SMEM>>>(out);
}

// round 16
// speedup vs baseline: 1.0388x; 1.0063x over previous
#include <cuda_runtime.h>
#include <cuda_bf16.h>
#include <stdint.h>
#include <math.h>

#define F_DIM 257
#define T_DIM 257
#define NB 4
#define NPIX (F_DIM * T_DIM)        // 66049
#define NTOT (NB * NPIX)            // 264196
#define SLOPE 0.2f

// ======================= scratch =======================
__device__ float d_h[NB * 2 * NPIX];                                // STFT (B,2,F,T)
__device__ __align__(16) unsigned short d_a0h[(size_t)NTOT * 64];   // NHWC bf16 hi
__device__ __align__(16) unsigned short d_a0l[(size_t)NTOT * 64];   // NHWC bf16 lo
__device__ __align__(16) unsigned short d_a1h[(size_t)NTOT * 64];
__device__ __align__(16) unsigned short d_a1l[(size_t)NTOT * 64];
__device__ __align__(16) float d_afin[(size_t)NTOT * 64];           // final conv3 out, fp32 NHWC
__device__ float d_wh[14 * 7 * 64];                                 // conv1 fp32 [ci][kw][o]
__device__ __align__(16) uint32_t d_wf[8 * 9 * 4 * 8 * 128];        // B frags [L*9+tap][ks][n8][lane][4]
__device__ float d_wl[578];                                         // last conv fp32
__device__ float d_win[512];                                        // stft window
__device__ __align__(8) float2 d_tw[256];                           // (cos,sin) 2πk/256
__device__ __align__(8) float2 d_cw[256];                           // (cos,sin) πf/256 combine

// ======================= small PTX helpers =======================
__device__ __forceinline__ uint32_t smem_u32(const void* p) {
    uint32_t a;
    asm("{ .reg .u64 t; cvta.to.shared.u64 t, %1; cvt.u32.u64 %0, t; }" : "=r"(a) : "l"(p));
    return a;
}
__device__ __forceinline__ void cp16(uint32_t dst, const void* src, int src_bytes) {
    asm volatile("cp.async.cg.shared.global [%0], [%1], 16, %2;"
                 :: "r"(dst), "l"(src), "r"(src_bytes) : "memory");
}
#define CP_COMMIT() asm volatile("cp.async.commit_group;" ::: "memory")
#define CP_WAIT(n)  asm volatile("cp.async.wait_group %0;" :: "n"(n) : "memory")

__device__ __forceinline__ void hmma(float* c, const uint32_t* a, const uint32_t* b) {
    asm volatile(
        "mma.sync.aligned.m16n8k16.row.col.f32.bf16.bf16.f32 "
        "{%0,%1,%2,%3}, {%4,%5,%6,%7}, {%8,%9}, {%0,%1,%2,%3};"
        : "+f"(c[0]), "+f"(c[1]), "+f"(c[2]), "+f"(c[3])
        : "r"(a[0]), "r"(a[1]), "r"(a[2]), "r"(a[3]), "r"(b[0]), "r"(b[1]));
}
__device__ __forceinline__ void ldmx4(uint32_t* r, uint32_t addr) {
    asm volatile("ldmatrix.sync.aligned.m8n8.x4.shared.b16 {%0,%1,%2,%3}, [%4];"
        : "=r"(r[0]), "=r"(r[1]), "=r"(r[2]), "=r"(r[3]) : "r"(addr));
}
__device__ __forceinline__ void stmx4(uint32_t addr, const uint32_t* r) {
    asm volatile("stmatrix.sync.aligned.m8n8.x4.shared.b16 [%0], {%1,%2,%3,%4};"
        :: "r"(addr), "r"(r[0]), "r"(r[1]), "r"(r[2]), "r"(r[3]) : "memory");
}
__device__ __forceinline__ uint32_t pack_bf2(float a, float b) {
    __nv_bfloat162 h = __floats2bfloat162_rn(a, b);
    return *reinterpret_cast<uint32_t*>(&h);
}

// ======================= weight-norm prep: conv1/last + DIRECT B-frag emission =======================
__global__ void prep_kernel(const float* __restrict__ v_h, const float* __restrict__ g_h,
                            const float* __restrict__ vs,  const float* __restrict__ gs,
                            const float* __restrict__ v_last, const float* __restrict__ g_last,
                            const float* __restrict__ b_last) {
    __shared__ float red[128];
    int bid = blockIdx.x, tid = threadIdx.x;

    if (bid == 577) {   // stft tables
        for (int i = tid; i < 512; i += 128)
            d_win[i] = 0.5f - 0.5f * cospif(i * (1.0f / 256.0f));
        for (int i = tid; i < 256; i += 128) {
            float ss, cc;
            sincospif(i * (1.0f / 128.0f), &ss, &cc);   // 2πi/256
            d_tw[i] = make_float2(cc, ss);
            sincospif(i * (1.0f / 256.0f), &ss, &cc);   // πi/256
            d_cw[i] = make_float2(cc, ss);
        }
        return;
    }

    const float* base; int n; float g; int o = 0;
    if (bid < 64)        { o = bid; base = v_h + o * 98; n = 98; g = g_h[o]; }
    else if (bid < 576)  { int L = (bid - 64) >> 6; o = (bid - 64) & 63;
                           base = vs + (size_t)(L * 64 + o) * 576; n = 576; g = gs[L * 64 + o]; }
    else                 { base = v_last; n = 576; g = g_last[0]; }

    float s = 0.f;
    for (int i = tid; i < n; i += 128) { float v = base[i]; s += v * v; }
    red[tid] = s; __syncthreads();
    for (int k = 64; k > 0; k >>= 1) { if (tid < k) red[tid] += red[tid + k]; __syncthreads(); }
    float scale = g * rsqrtf(red[0]);

    if (bid < 64) {
        for (int i = tid; i < n; i += 128) d_wh[i * 64 + o] = base[i] * scale;
    } else if (bid < 576) {
        // direct B-fragment emission: this block owns output channel o of layer L.
        // fragment lane = 4*(o&7) + l2, n8 = o>>3; per (tap,ks,l2): k pairs for r=0,1.
        int L = (bid - 64) >> 6;
        for (int i = tid; i < 144; i += 128) {
            int tap = i / 16, rem = i & 15, ks = rem >> 2, l2 = rem & 3;
            uint32_t w[4];
            #pragma unroll
            for (int r = 0; r < 2; r++) {
                int k0 = ks * 16 + r * 8 + l2 * 2;
                float w0 = base[k0 * 9 + tap] * scale;
                float w1 = base[(k0 + 1) * 9 + tap] * scale;
                __nv_bfloat16 h0 = __float2bfloat16(w0), h1 = __float2bfloat16(w1);
                __nv_bfloat16 l0 = __float2bfloat16(w0 - __bfloat162float(h0));
                __nv_bfloat16 l1 = __float2bfloat16(w1 - __bfloat162float(h1));
                w[r]     = ((uint32_t)__bfloat16_as_ushort(h1) << 16) | __bfloat16_as_ushort(h0);
                w[2 + r] = ((uint32_t)__bfloat16_as_ushort(l1) << 16) | __bfloat16_as_ushort(l0);
            }
            size_t idx = ((((size_t)(L * 9 + tap) * 4 + ks) * 8 + (o >> 3)) * 128
                          + (4 * (o & 7) + l2) * 4);
            *reinterpret_cast<uint4*>(d_wf + idx) = make_uint4(w[0], w[1], w[2], w[3]);
        }
    } else {
        for (int i = tid; i < n; i += 128) d_wl[i] = base[i] * scale;
        if (tid == 0) d_wl[576] = b_last[0];
    }
}

// ======================= STFT: one radix-2 DIT level, 256 threads =======================
__global__ __launch_bounds__(256) void stft_kernel(const float* __restrict__ x) {
    __shared__ float2 seo[256];    // (even, odd) windowed samples
    __shared__ float2 tw[256];     // (cos, sin) 2πk/256
    int t = blockIdx.x, b = blockIdx.y, tid = threadIdx.x;
    const float* xb = x + (size_t)b * 65536;

    {
        int n0 = tid * 2, n1 = n0 + 1;
        int i0 = t * 256 + n0 - 256;
        int i1 = i0 + 1;
        if (i0 < 0) i0 = -i0;
        if (i0 >= 65536) i0 = 131070 - i0;
        if (i1 < 0) i1 = -i1;
        if (i1 >= 65536) i1 = 131070 - i1;
        seo[tid] = make_float2(xb[i0] * d_win[n0], xb[i1] * d_win[n1]);
        tw[tid] = d_tw[tid];
    }
    __syncthreads();

    int f = tid;    // 0..255
    float eR = 0.f, eI = 0.f, oR = 0.f, oI = 0.f;
    int m = 0;
    #pragma unroll 8
    for (int k = 0; k < 256; k++) {
        float2 v = seo[k];
        float2 w = tw[m];
        eR += v.x * w.x;
        eI -= v.x * w.y;
        oR += v.y * w.x;
        oI -= v.y * w.y;
        m = (m + f) & 255;
    }
    // combine: X(f) = E(f) + e^{-iπf/256} O(f)
    float2 cw = d_cw[f];
    float re = eR + (cw.x * oR + cw.y * oI);
    float im = eI + (cw.x * oI - cw.y * oR);
    d_h[((size_t)(b * 2 + 0) * F_DIM + f) * T_DIM + t] = re;
    d_h[((size_t)(b * 2 + 1) * F_DIM + f) * T_DIM + t] = im;
    if (f == 0) {   // X(256) = ΣE − ΣO, imag exactly 0
        d_h[((size_t)(b * 2 + 0) * F_DIM + 256) * T_DIM + t] = eR - oR;
        d_h[((size_t)(b * 2 + 1) * F_DIM + 256) * T_DIM + t] = 0.f;
    }
}

// ======================= fused lower + conv1 + leaky -> smem-staged coalesced stores =======================
__global__ __launch_bounds__(256) void conv1_kernel(const float* __restrict__ b_h) {
    __shared__ float sw[1792];
    __shared__ float sb[64];
    __shared__ __align__(16) unsigned char stage[2][128 * 144];   // hi, lo px rows (144B stride)
    int tid = threadIdx.x;
    for (int i = tid; i < 1792; i += 256) sw[i] = d_wh[4480 + i];
    if (tid < 64) sb[tid] = b_h[tid];
    __syncthreads();

    int half = tid >> 7, px = tid & 127;
    int pid = blockIdx.x * 128 + px;

    if (pid < NTOT) {
        int b = pid / NPIX, rem = pid % NPIX;
        int f = rem / T_DIM, t = rem % T_DIM;

        const float shift5 = 154.15067982725832f;   // 1000*ln(7/6)
        float src  = (float)f - shift5;
        float lof  = floorf(src);
        float frac = src - lof;
        int   il   = (int)lof;
        const float* hb0 = d_h + ((size_t)(b * 2 + 0) * F_DIM) * T_DIM;
        const float* hb1 = d_h + ((size_t)(b * 2 + 1) * F_DIM) * T_DIM;

        float low[4][7];
        #pragma unroll
        for (int kw = 0; kw < 7; kw++) {
            int tt = t + kw - 3;
            bool tv = (tt >= 0) && (tt < T_DIM);
            float a0 = 0.f, a1 = 0.f, c0 = 0.f, c1 = 0.f, i0 = 0.f, i1 = 0.f;
            if (tv) {
                if (il >= 0 && il < F_DIM)          { a0 = hb0[il * T_DIM + tt];        a1 = hb1[il * T_DIM + tt]; }
                if (il + 1 >= 0 && il + 1 < F_DIM)  { c0 = hb0[(il + 1) * T_DIM + tt];  c1 = hb1[(il + 1) * T_DIM + tt]; }
                i0 = hb0[f * T_DIM + tt]; i1 = hb1[f * T_DIM + tt];
            }
            low[0][kw] = (1.0f - frac) * a0 + frac * c0;
            low[1][kw] = (1.0f - frac) * a1 + frac * c1;
            low[2][kw] = i0;
            low[3][kw] = i1;
        }

        float acc[32];
        #pragma unroll
        for (int o = 0; o < 32; o++) acc[o] = sb[half * 32 + o];
        #pragma unroll
        for (int ci = 0; ci < 4; ci++) {
            #pragma unroll
            for (int kw = 0; kw < 7; kw++) {
                float xv = low[ci][kw];
                const float* wp = &sw[(ci * 7 + kw) * 64 + half * 32];
                #pragma unroll
                for (int o = 0; o < 32; o++) acc[o] += xv * wp[o];
            }
        }

        unsigned char* sh = stage[0] + px * 144 + half * 64;
        unsigned char* sl = stage[1] + px * 144 + half * 64;
        #pragma unroll
        for (int c8 = 0; c8 < 4; c8++) {
            float yv[8], hv[8];
            #pragma unroll
            for (int j = 0; j < 8; j++) {
                float y = acc[c8 * 8 + j];
                y = (y > 0.f) ? y : SLOPE * y;
                yv[j] = y;
                hv[j] = __bfloat162float(__float2bfloat16(y));
            }
            uint4 qh, ql;
            qh.x = pack_bf2(hv[0], hv[1]); qh.y = pack_bf2(hv[2], hv[3]);
            qh.z = pack_bf2(hv[4], hv[5]); qh.w = pack_bf2(hv[6], hv[7]);
            ql.x = pack_bf2(yv[0] - hv[0], yv[1] - hv[1]); ql.y = pack_bf2(yv[2] - hv[2], yv[3] - hv[3]);
            ql.z = pack_bf2(yv[4] - hv[4], yv[5] - hv[5]); ql.w = pack_bf2(yv[6] - hv[6], yv[7] - hv[7]);
            *reinterpret_cast<uint4*>(sh + c8 * 16) = qh;
            *reinterpret_cast<uint4*>(sl + c8 * 16) = ql;
        }
    }
    __syncthreads();

    // coalesced writeout: 2 arrays x 128 px x 8 chunks of 16B
    size_t pid0 = (size_t)blockIdx.x * 128;
    #pragma unroll
    for (int i0 = 0; i0 < 2048; i0 += 256) {
        int i = i0 + tid;
        int arr = i >> 10, r2 = i & 1023, p = r2 >> 3, col = r2 & 7;
        if (pid0 + p < NTOT) {
            uint4 v = *reinterpret_cast<const uint4*>(stage[arr] + p * 144 + col * 16);
            unsigned short* outp = arr ? d_a0l : d_a0h;
            *reinterpret_cast<uint4*>(outp + (pid0 + p) * 64 + col * 8) = v;
        }
    }
}

// ======================= dilated 3x3 conv: templated D + LAST fp32 finale =======================
#define AT_STRIDE 144
#define STAGE_BYTES (192 * AT_STRIDE)          // 4 pf rows x 48 t-slots
#define SM_BIAS_OFF (4 * STAGE_BYTES)          // 110592
#define CONV3_SMEM (SM_BIAS_OFF + 256)

template <int D, bool LAST>
__global__ __launch_bounds__(256, 2) void conv3_mma(int layer, const float* __restrict__ bs) {
    extern __shared__ __align__(16) unsigned char smem[];
    uint32_t sb = smem_u32(smem);
    int tid = threadIdx.x, wid = tid >> 5, lid = tid & 31;
    int t0 = blockIdx.x * 32, f0 = blockIdx.y * 4, b = blockIdx.z;
    constexpr int HW  = 32 + 2 * D;
    constexpr int HW8 = HW * 8;
    constexpr int E   = 4 * HW8;

    const unsigned short* inH = (layer & 1) ? d_a1h : d_a0h;
    const unsigned short* inL = (layer & 1) ? d_a1l : d_a0l;
    unsigned short* outH = (layer & 1) ? d_a0h : d_a1h;
    unsigned short* outL = (layer & 1) ? d_a0l : d_a1l;

    if (tid < 64) *reinterpret_cast<float*>(smem + SM_BIAS_OFF + tid * 4) = bs[layer * 64 + tid];

    int mrow0 = (wid & 3) * 32;
    int ocw   = (wid >> 2) * 32;
    int n8b   = (wid >> 2) * 4;

    int mat = lid >> 3, rowin = lid & 7;
    uint32_t laneoff = (uint32_t)(((mat & 1) * 8 + rowin) * AT_STRIDE + (mat >> 1) * 16);
    uint32_t pfoff   = (uint32_t)((mrow0 >> 5) * 48 * AT_STRIDE);

    float acc[2][4][4];
    #pragma unroll
    for (int m = 0; m < 2; m++)
        #pragma unroll
        for (int n = 0; n < 4; n++)
            #pragma unroll
            for (int r = 0; r < 4; r++) acc[m][n][r] = 0.f;

    // ---- prologue: burst-load group 0 (df = -D) into stage 0 ----
    {
        uint32_t baseH = sb, baseL = sb + STAGE_BYTES;
        #pragma unroll
        for (int e0 = 0; e0 < E; e0 += 256) {
            int e = e0 + tid;
            if (e < E) {
                int pf = e / HW8;
                int r = e - pf * HW8;
                int tl = r >> 3, cb = (r & 7) * 16;
                int gf = f0 + pf - D, gt = t0 - D + tl;
                bool ok = ((unsigned)gf < F_DIM) && ((unsigned)gt < T_DIM);
                size_t ridx = ok ? ((((size_t)b * F_DIM + gf) * T_DIM + gt) * 64) : 0;
                uint32_t off = (uint32_t)(pf * 48 + tl) * AT_STRIDE + cb;
                cp16(baseH + off, (const unsigned char*)inH + ridx * 2 + cb, ok ? 16 : 0);
                cp16(baseL + off, (const unsigned char*)inL + ridx * 2 + cb, ok ? 16 : 0);
            }
        }
        CP_COMMIT();
    }

    // ---- prime B-frag prefetch: tap 0, ks 0 ----
    const uint4* wfbase = reinterpret_cast<const uint4*>(d_wf) + (size_t)(layer * 9) * 1024;
    uint4 qbuf[4];
    #pragma unroll
    for (int n = 0; n < 4; n++)
        qbuf[n] = __ldg(&wfbase[(n8b + n) * 32 + lid]);

    #pragma unroll
    for (int g = 0; g < 3; g++) {
        CP_WAIT(0);
        __syncthreads();

        uint32_t aH = sb + (uint32_t)(g & 1) * 2u * STAGE_BYTES;
        uint32_t aL = aH + STAGE_BYTES;
        uint32_t nH = sb + (uint32_t)((g + 1) & 1) * 2u * STAGE_BYTES;
        uint32_t nL = nH + STAGE_BYTES;
        const int dfn = g * D;

        #pragma unroll
        for (int kt = 0; kt < 3; kt++) {
            int tap = g * 3 + kt;
            const uint4* wb = wfbase + (size_t)tap * 1024;
            uint32_t abase = pfoff + (uint32_t)(kt * D) * AT_STRIDE + laneoff;

            #pragma unroll
            for (int ks = 0; ks < 4; ks++) {
                uint32_t bh[4][2], bl[4][2];
                #pragma unroll
                for (int n = 0; n < 4; n++) {
                    bh[n][0] = qbuf[n].x; bh[n][1] = qbuf[n].y;
                    bl[n][0] = qbuf[n].z; bl[n][1] = qbuf[n].w;
                }
                if (!((g == 2) && (kt == 2) && (ks == 3))) {
                    const uint4* wbn = (ks < 3) ? wb : (wb + 1024);
                    int ksn = (ks < 3) ? (ks + 1) : 0;
                    #pragma unroll
                    for (int n = 0; n < 4; n++)
                        qbuf[n] = __ldg(&wbn[(ksn * 8 + n8b + n) * 32 + lid]);
                }

                uint32_t ah[2][4], al[2][4];
                ldmx4(ah[0], aH + abase + ks * 32);
                ldmx4(ah[1], aH + abase + 16 * AT_STRIDE + ks * 32);
                ldmx4(al[0], aL + abase + ks * 32);
                ldmx4(al[1], aL + abase + 16 * AT_STRIDE + ks * 32);

                #pragma unroll
                for (int m = 0; m < 2; m++)
                    #pragma unroll
                    for (int n = 0; n < 4; n++) hmma(acc[m][n], ah[m], bh[n]);
                #pragma unroll
                for (int m = 0; m < 2; m++)
                    #pragma unroll
                    for (int n = 0; n < 4; n++) hmma(acc[m][n], ah[m], bl[n]);
                #pragma unroll
                for (int m = 0; m < 2; m++)
                    #pragma unroll
                    for (int n = 0; n < 4; n++) hmma(acc[m][n], al[m], bh[n]);

                // interleaved chunk of next group's loads; single commit per group
                if (g < 2) {
                    int e = (kt * 4 + ks) * 256 + tid;
                    if (e < E) {
                        int pf = e / HW8;
                        int r = e - pf * HW8;
                        int tl = r >> 3, cb = (r & 7) * 16;
                        int gf = f0 + pf + dfn, gt = t0 - D + tl;
                        bool ok = ((unsigned)gf < F_DIM) && ((unsigned)gt < T_DIM);
                        size_t ridx = ok ? ((((size_t)b * F_DIM + gf) * T_DIM + gt) * 64) : 0;
                        uint32_t off = (uint32_t)(pf * 48 + tl) * AT_STRIDE + cb;
                        cp16(nH + off, (const unsigned char*)inH + ridx * 2 + cb, ok ? 16 : 0);
                        cp16(nL + off, (const unsigned char*)inL + ridx * 2 + cb, ok ? 16 : 0);
                    }
                }
            }
        }
        if (g < 2) CP_COMMIT();
    }
    __syncthreads();

    const float* bias = reinterpret_cast<const float*>(smem + SM_BIAS_OFF);

    if (LAST) {
        // ---- finale: stage fp32 rows in smem (272B stride), then coalesced writeout ----
        float* fst = reinterpret_cast<float*>(smem);
        #pragma unroll
        for (int m = 0; m < 2; m++) {
            #pragma unroll
            for (int r2 = 0; r2 < 2; r2++) {
                int p = mrow0 + m * 16 + (lid >> 2) + r2 * 8;
                #pragma unroll
                for (int n = 0; n < 4; n++) {
                    int oc = ocw + n * 8 + (lid & 3) * 2;
                    float y0 = acc[m][n][r2 * 2 + 0] + bias[oc];
                    float y1 = acc[m][n][r2 * 2 + 1] + bias[oc + 1];
                    y0 = (y0 > 0.f) ? y0 : SLOPE * y0;
                    y1 = (y1 > 0.f) ? y1 : SLOPE * y1;
                    *reinterpret_cast<float2*>(fst + p * 68 + oc) = make_float2(y0, y1);
                }
            }
        }
        __syncthreads();
        // writeout: 128 px x 16 chunks of 16B
        #pragma unroll
        for (int i0 = 0; i0 < 2048; i0 += 256) {
            int i = i0 + tid;
            int p = i >> 4, col = i & 15;
            int gf = f0 + (p >> 5), gt = t0 + (p & 31);
            if (gf < F_DIM && gt < T_DIM) {
                float4 v = *reinterpret_cast<const float4*>(fst + p * 68 + col * 4);
                size_t ridx = (((size_t)b * F_DIM + gf) * T_DIM + gt) * 64 + col * 4;
                *reinterpret_cast<float4*>(d_afin + ridx) = v;
            }
        }
    } else {
        // ---- epilogue: bias + leaky + hi/lo split, stmatrix staging, coalesced STG.128 ----
        uint32_t stg = sb + (uint32_t)wid * 5120u;
        unsigned char* stgp = smem + wid * 5120;

        #pragma unroll
        for (int m = 0; m < 2; m++) {
            uint32_t hreg[2][4], lreg[2][4];
            #pragma unroll
            for (int n = 0; n < 4; n++) {
                int oc = ocw + n * 8 + (lid & 3) * 2;
                float b0 = bias[oc], b1 = bias[oc + 1];
                #pragma unroll
                for (int r2 = 0; r2 < 2; r2++) {
                    float y0 = acc[m][n][r2 * 2 + 0] + b0;
                    float y1 = acc[m][n][r2 * 2 + 1] + b1;
                    y0 = (y0 > 0.f) ? y0 : SLOPE * y0;
                    y1 = (y1 > 0.f) ? y1 : SLOPE * y1;
                    float h0 = __bfloat162float(__float2bfloat16(y0));
                    float h1 = __bfloat162float(__float2bfloat16(y1));
                    hreg[r2][n] = pack_bf2(h0, h1);
                    lreg[r2][n] = pack_bf2(y0 - h0, y1 - h1);
                }
            }
            uint32_t arow = stg + (uint32_t)((m * 16 + rowin) * 80 + mat * 16);
            stmx4(arow,                 hreg[0]);
            stmx4(arow + 8 * 80,        hreg[1]);
            stmx4(arow + 2560,          lreg[0]);
            stmx4(arow + 2560 + 8 * 80, lreg[1]);
        }
        __syncwarp();

        int gfx = f0 + (wid & 3);
        if (gfx < F_DIM) {
            #pragma unroll
            for (int it = 0; it < 4; it++) {
                int p = it * 8 + (lid >> 2);
                int gt = t0 + p;
                uint4 vh = *reinterpret_cast<const uint4*>(stgp + p * 80 + (lid & 3) * 16);
                uint4 vl = *reinterpret_cast<const uint4*>(stgp + 2560 + p * 80 + (lid & 3) * 16);
                if (gt < T_DIM) {
                    size_t ridx = (((size_t)b * F_DIM + gfx) * T_DIM + gt) * 64 + ocw + (lid & 3) * 8;
                    *reinterpret_cast<uint4*>(outH + ridx) = vh;
                    *reinterpret_cast<uint4*>(outL + ridx) = vl;
                }
            }
        }
    }
}

// ======================= last conv (64 -> 1, 3x3, pad 1): fp32 smem-tiled =======================
#define L2_STRIDE 272                     // 256B px row + 16B pad (conflict-free LDS.128 phases)
#define L2_PX 340                         // 10 f x 34 t halo pixels
#define L2_SW (L2_PX * L2_STRIDE)         // 92480
#define L2_SMEM (L2_SW + 2320)

__global__ __launch_bounds__(256, 2) void last_kernel(float* __restrict__ out) {
    extern __shared__ __align__(16) unsigned char lsm[];
    uint32_t sbx = smem_u32(lsm);
    float* sw = reinterpret_cast<float*>(lsm + L2_SW);
    int tid = threadIdx.x;
    int t0 = blockIdx.x * 32, f0 = blockIdx.y * 8, b = blockIdx.z;

    for (int i = tid; i < 577; i += 256) sw[i] = d_wl[i];

    for (int e = tid; e < L2_PX * 16; e += 256) {
        int p = e >> 4, cb = (e & 15) * 16;
        int fl = p / 34, tl = p - fl * 34;
        int gf = f0 - 1 + fl, gt = t0 - 1 + tl;
        bool ok = ((unsigned)gf < F_DIM) && ((unsigned)gt < T_DIM);
        size_t ridx = ok ? ((((size_t)b * F_DIM + gf) * T_DIM + gt) * 64) : 0;
        cp16(sbx + p * L2_STRIDE + cb, (const unsigned char*)d_afin + ridx * 4 + cb, ok ? 16 : 0);
    }
    CP_COMMIT(); CP_WAIT(0);
    __syncthreads();

    int fl = tid >> 5, tl = tid & 31;
    int f = f0 + fl, t = t0 + tl;
    if (f >= F_DIM || t >= T_DIM) return;

    float acc = sw[576];
    #pragma unroll
    for (int kf = 0; kf < 3; kf++) {
        #pragma unroll
        for (int kt = 0; kt < 3; kt++) {
            int p = (fl + kf) * 34 + (tl + kt);
            const float4* px = reinterpret_cast<const float4*>(lsm + p * L2_STRIDE);
            int wi = kf * 3 + kt;
            #pragma unroll
            for (int c4 = 0; c4 < 16; c4++) {
                float4 v = px[c4];
                int c = c4 * 4;
                acc += v.x * sw[c * 9 + wi];
                acc += v.y * sw[(c + 1) * 9 + wi];
                acc += v.z * sw[(c + 2) * 9 + wi];
                acc += v.w * sw[(c + 3) * 9 + wi];
            }
        }
    }
    out[(size_t)b * NPIX + (size_t)f * T_DIM + t] = acc;
}

// ======================= launch =======================
extern "C" void kernel_launch(void* const* d_in, const int* in_sizes, int n_in,
                              void* d_out, int out_size) {
    const float* x      = (const float*)d_in[0];
    const float* v_h    = (const float*)d_in[1];
    const float* g_h    = (const float*)d_in[2];
    const float* b_h    = (const float*)d_in[3];
    const float* vs     = (const float*)d_in[4];
    const float* gs     = (const float*)d_in[5];
    const float* bs     = (const float*)d_in[6];
    const float* v_last = (const float*)d_in[7];
    const float* g_last = (const float*)d_in[8];
    const float* b_last = (const float*)d_in[9];
    float* out = (float*)d_out;

    cudaFuncSetAttribute(conv3_mma<1, false>, cudaFuncAttributeMaxDynamicSharedMemorySize, CONV3_SMEM);
    cudaFuncSetAttribute(conv3_mma<2, false>, cudaFuncAttributeMaxDynamicSharedMemorySize, CONV3_SMEM);
    cudaFuncSetAttribute(conv3_mma<3, false>, cudaFuncAttributeMaxDynamicSharedMemorySize, CONV3_SMEM);
    cudaFuncSetAttribute(conv3_mma<4, false>, cudaFuncAttributeMaxDynamicSharedMemorySize, CONV3_SMEM);
    cudaFuncSetAttribute(conv3_mma<5, false>, cudaFuncAttributeMaxDynamicSharedMemorySize, CONV3_SMEM);
    cudaFuncSetAttribute(conv3_mma<6, false>, cudaFuncAttributeMaxDynamicSharedMemorySize, CONV3_SMEM);
    cudaFuncSetAttribute(conv3_mma<7, false>, cudaFuncAttributeMaxDynamicSharedMemorySize, CONV3_SMEM);
    cudaFuncSetAttribute(conv3_mma<8, true>,  cudaFuncAttributeMaxDynamicSharedMemorySize, CONV3_SMEM);
    cudaFuncSetAttribute(last_kernel, cudaFuncAttributeMaxDynamicSharedMemorySize, L2_SMEM);

    prep_kernel<<<578, 128>>>(v_h, g_h, vs, gs, v_last, g_last, b_last);
    stft_kernel<<<dim3(257, NB), 256>>>(x);
    conv1_kernel<<<(NTOT + 127) / 128, 256>>>(b_h);

    dim3 cg(9, 65, NB);
    conv3_mma<1, false><<<cg, 256, CONV3_SMEM>>>(0, bs);
    conv3_mma<2, false><<<cg, 256, CONV3_SMEM>>>(1, bs);
    conv3_mma<3, false><<<cg, 256, CONV3_SMEM>>>(2, bs);
    conv3_mma<4, false><<<cg, 256, CONV3_SMEM>>>(3, bs);
    conv3_mma<5, false><<<cg, 256, CONV3_SMEM>>>(4, bs);
    conv3_mma<6, false><<<cg, 256, CONV3_SMEM>>>(5, bs);
    conv3_mma<7, false><<<cg, 256, CONV3_SMEM>>>(6, bs);
    conv3_mma<8, true><<<cg, 256, CONV3_SMEM>>>(7, bs);

    last_kernel<<<dim3(9, 33, NB), 256, L2_SMEM>>>(out);
}

// round 17
// speedup vs baseline: 1.0391x; 1.0003x over previous
#include <cuda_runtime.h>
#include <cuda_bf16.h>
#include <stdint.h>
#include <math.h>

#define F_DIM 257
#define T_DIM 257
#define NB 4
#define NPIX (F_DIM * T_DIM)        // 66049
#define NTOT (NB * NPIX)            // 264196
#define SLOPE 0.2f

// ======================= scratch =======================
__device__ float d_h[NB * 2 * NPIX];                                // STFT (B,2,F,T)
__device__ __align__(16) unsigned short d_a0h[(size_t)NTOT * 64];   // NHWC bf16 hi
__device__ __align__(16) unsigned short d_a0l[(size_t)NTOT * 64];   // NHWC bf16 lo
__device__ __align__(16) unsigned short d_a1h[(size_t)NTOT * 64];
__device__ __align__(16) unsigned short d_a1l[(size_t)NTOT * 64];
__device__ __align__(16) float d_afin[(size_t)NTOT * 64];           // final conv3 out, fp32 NHWC
__device__ float d_wh[14 * 7 * 64];                                 // conv1 fp32 [ci][kw][o]
__device__ __align__(16) uint32_t d_wf[8 * 9 * 4 * 8 * 128];        // B frags [L*9+tap][ks][n8][lane][4]
__device__ float d_wl[578];                                         // last conv fp32
__device__ float d_win[512];                                        // stft window
__device__ __align__(8) float2 d_tw[256];                           // (cos,sin) 2πk/256
__device__ __align__(8) float2 d_cw[256];                           // (cos,sin) πf/256 combine

// ======================= small PTX helpers =======================
__device__ __forceinline__ uint32_t smem_u32(const void* p) {
    uint32_t a;
    asm("{ .reg .u64 t; cvta.to.shared.u64 t, %1; cvt.u32.u64 %0, t; }" : "=r"(a) : "l"(p));
    return a;
}
__device__ __forceinline__ void cp16(uint32_t dst, const void* src, int src_bytes) {
    asm volatile("cp.async.cg.shared.global [%0], [%1], 16, %2;"
                 :: "r"(dst), "l"(src), "r"(src_bytes) : "memory");
}
#define CP_COMMIT() asm volatile("cp.async.commit_group;" ::: "memory")
#define CP_WAIT(n)  asm volatile("cp.async.wait_group %0;" :: "n"(n) : "memory")

__device__ __forceinline__ void hmma(float* c, const uint32_t* a, const uint32_t* b) {
    asm volatile(
        "mma.sync.aligned.m16n8k16.row.col.f32.bf16.bf16.f32 "
        "{%0,%1,%2,%3}, {%4,%5,%6,%7}, {%8,%9}, {%0,%1,%2,%3};"
        : "+f"(c[0]), "+f"(c[1]), "+f"(c[2]), "+f"(c[3])
        : "r"(a[0]), "r"(a[1]), "r"(a[2]), "r"(a[3]), "r"(b[0]), "r"(b[1]));
}
__device__ __forceinline__ void ldmx4(uint32_t* r, uint32_t addr) {
    asm volatile("ldmatrix.sync.aligned.m8n8.x4.shared.b16 {%0,%1,%2,%3}, [%4];"
        : "=r"(r[0]), "=r"(r[1]), "=r"(r[2]), "=r"(r[3]) : "r"(addr));
}
__device__ __forceinline__ void stmx4(uint32_t addr, const uint32_t* r) {
    asm volatile("stmatrix.sync.aligned.m8n8.x4.shared.b16 [%0], {%1,%2,%3,%4};"
        :: "r"(addr), "r"(r[0]), "r"(r[1]), "r"(r[2]), "r"(r[3]) : "memory");
}
__device__ __forceinline__ uint32_t pack_bf2(float a, float b) {
    __nv_bfloat162 h = __floats2bfloat162_rn(a, b);
    return *reinterpret_cast<uint32_t*>(&h);
}

// ======================= weight-norm prep: conv1/last + DIRECT B-frag emission =======================
__global__ void prep_kernel(const float* __restrict__ v_h, const float* __restrict__ g_h,
                            const float* __restrict__ vs,  const float* __restrict__ gs,
                            const float* __restrict__ v_last, const float* __restrict__ g_last,
                            const float* __restrict__ b_last) {
    __shared__ float red[128];
    int bid = blockIdx.x, tid = threadIdx.x;

    if (bid == 577) {   // stft tables
        for (int i = tid; i < 512; i += 128)
            d_win[i] = 0.5f - 0.5f * cospif(i * (1.0f / 256.0f));
        for (int i = tid; i < 256; i += 128) {
            float ss, cc;
            sincospif(i * (1.0f / 128.0f), &ss, &cc);   // 2πi/256
            d_tw[i] = make_float2(cc, ss);
            sincospif(i * (1.0f / 256.0f), &ss, &cc);   // πi/256
            d_cw[i] = make_float2(cc, ss);
        }
        return;
    }

    const float* base; int n; float g; int o = 0;
    if (bid < 64)        { o = bid; base = v_h + o * 98; n = 98; g = g_h[o]; }
    else if (bid < 576)  { int L = (bid - 64) >> 6; o = (bid - 64) & 63;
                           base = vs + (size_t)(L * 64 + o) * 576; n = 576; g = gs[L * 64 + o]; }
    else                 { base = v_last; n = 576; g = g_last[0]; }

    float s = 0.f;
    for (int i = tid; i < n; i += 128) { float v = base[i]; s += v * v; }
    red[tid] = s; __syncthreads();
    for (int k = 64; k > 0; k >>= 1) { if (tid < k) red[tid] += red[tid + k]; __syncthreads(); }
    float scale = g * rsqrtf(red[0]);

    if (bid < 64) {
        for (int i = tid; i < n; i += 128) d_wh[i * 64 + o] = base[i] * scale;
    } else if (bid < 576) {
        // direct B-fragment emission: this block owns output channel o of layer L.
        int L = (bid - 64) >> 6;
        for (int i = tid; i < 144; i += 128) {
            int tap = i / 16, rem = i & 15, ks = rem >> 2, l2 = rem & 3;
            uint32_t w[4];
            #pragma unroll
            for (int r = 0; r < 2; r++) {
                int k0 = ks * 16 + r * 8 + l2 * 2;
                float w0 = base[k0 * 9 + tap] * scale;
                float w1 = base[(k0 + 1) * 9 + tap] * scale;
                __nv_bfloat16 h0 = __float2bfloat16(w0), h1 = __float2bfloat16(w1);
                __nv_bfloat16 l0 = __float2bfloat16(w0 - __bfloat162float(h0));
                __nv_bfloat16 l1 = __float2bfloat16(w1 - __bfloat162float(h1));
                w[r]     = ((uint32_t)__bfloat16_as_ushort(h1) << 16) | __bfloat16_as_ushort(h0);
                w[2 + r] = ((uint32_t)__bfloat16_as_ushort(l1) << 16) | __bfloat16_as_ushort(l0);
            }
            size_t idx = ((((size_t)(L * 9 + tap) * 4 + ks) * 8 + (o >> 3)) * 128
                          + (4 * (o & 7) + l2) * 4);
            *reinterpret_cast<uint4*>(d_wf + idx) = make_uint4(w[0], w[1], w[2], w[3]);
        }
    } else {
        for (int i = tid; i < n; i += 128) d_wl[i] = base[i] * scale;
        if (tid == 0) d_wl[576] = b_last[0];
    }
}

// ======================= STFT: one radix-2 DIT level, 256 threads =======================
__global__ __launch_bounds__(256) void stft_kernel(const float* __restrict__ x) {
    __shared__ float2 seo[256];
    __shared__ float2 tw[256];
    int t = blockIdx.x, b = blockIdx.y, tid = threadIdx.x;
    const float* xb = x + (size_t)b * 65536;

    {
        int n0 = tid * 2, n1 = n0 + 1;
        int i0 = t * 256 + n0 - 256;
        int i1 = i0 + 1;
        if (i0 < 0) i0 = -i0;
        if (i0 >= 65536) i0 = 131070 - i0;
        if (i1 < 0) i1 = -i1;
        if (i1 >= 65536) i1 = 131070 - i1;
        seo[tid] = make_float2(xb[i0] * d_win[n0], xb[i1] * d_win[n1]);
        tw[tid] = d_tw[tid];
    }
    __syncthreads();

    int f = tid;    // 0..255
    float eR = 0.f, eI = 0.f, oR = 0.f, oI = 0.f;
    int m = 0;
    #pragma unroll 8
    for (int k = 0; k < 256; k++) {
        float2 v = seo[k];
        float2 w = tw[m];
        eR += v.x * w.x;
        eI -= v.x * w.y;
        oR += v.y * w.x;
        oI -= v.y * w.y;
        m = (m + f) & 255;
    }
    float2 cw = d_cw[f];
    float re = eR + (cw.x * oR + cw.y * oI);
    float im = eI + (cw.x * oI - cw.y * oR);
    d_h[((size_t)(b * 2 + 0) * F_DIM + f) * T_DIM + t] = re;
    d_h[((size_t)(b * 2 + 1) * F_DIM + f) * T_DIM + t] = im;
    if (f == 0) {
        d_h[((size_t)(b * 2 + 0) * F_DIM + 256) * T_DIM + t] = eR - oR;
        d_h[((size_t)(b * 2 + 1) * F_DIM + 256) * T_DIM + t] = 0.f;
    }
}

// ======================= fused lower + conv1 + leaky -> smem-staged coalesced stores =======================
__global__ __launch_bounds__(256) void conv1_kernel(const float* __restrict__ b_h) {
    __shared__ float sw[1792];
    __shared__ float sb[64];
    __shared__ __align__(16) unsigned char stage[2][128 * 144];
    int tid = threadIdx.x;
    for (int i = tid; i < 1792; i += 256) sw[i] = d_wh[4480 + i];
    if (tid < 64) sb[tid] = b_h[tid];
    __syncthreads();

    int half = tid >> 7, px = tid & 127;
    int pid = blockIdx.x * 128 + px;

    if (pid < NTOT) {
        int b = pid / NPIX, rem = pid % NPIX;
        int f = rem / T_DIM, t = rem % T_DIM;

        const float shift5 = 154.15067982725832f;   // 1000*ln(7/6)
        float src  = (float)f - shift5;
        float lof  = floorf(src);
        float frac = src - lof;
        int   il   = (int)lof;
        const float* hb0 = d_h + ((size_t)(b * 2 + 0) * F_DIM) * T_DIM;
        const float* hb1 = d_h + ((size_t)(b * 2 + 1) * F_DIM) * T_DIM;

        float low[4][7];
        #pragma unroll
        for (int kw = 0; kw < 7; kw++) {
            int tt = t + kw - 3;
            bool tv = (tt >= 0) && (tt < T_DIM);
            float a0 = 0.f, a1 = 0.f, c0 = 0.f, c1 = 0.f, i0 = 0.f, i1 = 0.f;
            if (tv) {
                if (il >= 0 && il < F_DIM)          { a0 = hb0[il * T_DIM + tt];        a1 = hb1[il * T_DIM + tt]; }
                if (il + 1 >= 0 && il + 1 < F_DIM)  { c0 = hb0[(il + 1) * T_DIM + tt];  c1 = hb1[(il + 1) * T_DIM + tt]; }
                i0 = hb0[f * T_DIM + tt]; i1 = hb1[f * T_DIM + tt];
            }
            low[0][kw] = (1.0f - frac) * a0 + frac * c0;
            low[1][kw] = (1.0f - frac) * a1 + frac * c1;
            low[2][kw] = i0;
            low[3][kw] = i1;
        }

        float acc[32];
        #pragma unroll
        for (int o = 0; o < 32; o++) acc[o] = sb[half * 32 + o];
        #pragma unroll
        for (int ci = 0; ci < 4; ci++) {
            #pragma unroll
            for (int kw = 0; kw < 7; kw++) {
                float xv = low[ci][kw];
                const float* wp = &sw[(ci * 7 + kw) * 64 + half * 32];
                #pragma unroll
                for (int o = 0; o < 32; o++) acc[o] += xv * wp[o];
            }
        }

        unsigned char* sh = stage[0] + px * 144 + half * 64;
        unsigned char* sl = stage[1] + px * 144 + half * 64;
        #pragma unroll
        for (int c8 = 0; c8 < 4; c8++) {
            float yv[8], hv[8];
            #pragma unroll
            for (int j = 0; j < 8; j++) {
                float y = acc[c8 * 8 + j];
                y = (y > 0.f) ? y : SLOPE * y;
                yv[j] = y;
                hv[j] = __bfloat162float(__float2bfloat16(y));
            }
            uint4 qh, ql;
            qh.x = pack_bf2(hv[0], hv[1]); qh.y = pack_bf2(hv[2], hv[3]);
            qh.z = pack_bf2(hv[4], hv[5]); qh.w = pack_bf2(hv[6], hv[7]);
            ql.x = pack_bf2(yv[0] - hv[0], yv[1] - hv[1]); ql.y = pack_bf2(yv[2] - hv[2], yv[3] - hv[3]);
            ql.z = pack_bf2(yv[4] - hv[4], yv[5] - hv[5]); ql.w = pack_bf2(yv[6] - hv[6], yv[7] - hv[7]);
            *reinterpret_cast<uint4*>(sh + c8 * 16) = qh;
            *reinterpret_cast<uint4*>(sl + c8 * 16) = ql;
        }
    }
    __syncthreads();

    size_t pid0 = (size_t)blockIdx.x * 128;
    #pragma unroll
    for (int i0 = 0; i0 < 2048; i0 += 256) {
        int i = i0 + tid;
        int arr = i >> 10, r2 = i & 1023, p = r2 >> 3, col = r2 & 7;
        if (pid0 + p < NTOT) {
            uint4 v = *reinterpret_cast<const uint4*>(stage[arr] + p * 144 + col * 16);
            unsigned short* outp = arr ? d_a0l : d_a0h;
            *reinterpret_cast<uint4*>(outp + (pid0 + p) * 64 + col * 8) = v;
        }
    }
}

// ======================= dilated 3x3 conv: templated D + LAST fp32 finale =======================
// Interleaved loads FRONT-LOADED into the first 6 ks-iterations of each group so the
// last cp.async has ~half a group of compute to land before the CP_WAIT(0).
#define AT_STRIDE 144
#define STAGE_BYTES (192 * AT_STRIDE)          // 4 pf rows x 48 t-slots
#define SM_BIAS_OFF (4 * STAGE_BYTES)          // 110592
#define CONV3_SMEM (SM_BIAS_OFF + 256)

template <int D, bool LAST>
__global__ __launch_bounds__(256, 2) void conv3_mma(int layer, const float* __restrict__ bs) {
    extern __shared__ __align__(16) unsigned char smem[];
    uint32_t sb = smem_u32(smem);
    int tid = threadIdx.x, wid = tid >> 5, lid = tid & 31;
    int t0 = blockIdx.x * 32, f0 = blockIdx.y * 4, b = blockIdx.z;
    constexpr int HW  = 32 + 2 * D;
    constexpr int HW8 = HW * 8;
    constexpr int E   = 4 * HW8;

    const unsigned short* inH = (layer & 1) ? d_a1h : d_a0h;
    const unsigned short* inL = (layer & 1) ? d_a1l : d_a0l;
    unsigned short* outH = (layer & 1) ? d_a0h : d_a1h;
    unsigned short* outL = (layer & 1) ? d_a0l : d_a1l;

    if (tid < 64) *reinterpret_cast<float*>(smem + SM_BIAS_OFF + tid * 4) = bs[layer * 64 + tid];

    int mrow0 = (wid & 3) * 32;
    int ocw   = (wid >> 2) * 32;
    int n8b   = (wid >> 2) * 4;

    int mat = lid >> 3, rowin = lid & 7;
    uint32_t laneoff = (uint32_t)(((mat & 1) * 8 + rowin) * AT_STRIDE + (mat >> 1) * 16);
    uint32_t pfoff   = (uint32_t)((mrow0 >> 5) * 48 * AT_STRIDE);

    float acc[2][4][4];
    #pragma unroll
    for (int m = 0; m < 2; m++)
        #pragma unroll
        for (int n = 0; n < 4; n++)
            #pragma unroll
            for (int r = 0; r < 4; r++) acc[m][n][r] = 0.f;

    // ---- prologue: burst-load group 0 (df = -D) into stage 0 ----
    {
        uint32_t baseH = sb, baseL = sb + STAGE_BYTES;
        #pragma unroll
        for (int e0 = 0; e0 < E; e0 += 256) {
            int e = e0 + tid;
            if (e < E) {
                int pf = e / HW8;
                int r = e - pf * HW8;
                int tl = r >> 3, cb = (r & 7) * 16;
                int gf = f0 + pf - D, gt = t0 - D + tl;
                bool ok = ((unsigned)gf < F_DIM) && ((unsigned)gt < T_DIM);
                size_t ridx = ok ? ((((size_t)b * F_DIM + gf) * T_DIM + gt) * 64) : 0;
                uint32_t off = (uint32_t)(pf * 48 + tl) * AT_STRIDE + cb;
                cp16(baseH + off, (const unsigned char*)inH + ridx * 2 + cb, ok ? 16 : 0);
                cp16(baseL + off, (const unsigned char*)inL + ridx * 2 + cb, ok ? 16 : 0);
            }
        }
        CP_COMMIT();
    }

    // ---- prime B-frag prefetch: tap 0, ks 0 ----
    const uint4* wfbase = reinterpret_cast<const uint4*>(d_wf) + (size_t)(layer * 9) * 1024;
    uint4 qbuf[4];
    #pragma unroll
    for (int n = 0; n < 4; n++)
        qbuf[n] = __ldg(&wfbase[(n8b + n) * 32 + lid]);

    #pragma unroll
    for (int g = 0; g < 3; g++) {
        CP_WAIT(0);
        __syncthreads();

        uint32_t aH = sb + (uint32_t)(g & 1) * 2u * STAGE_BYTES;
        uint32_t aL = aH + STAGE_BYTES;
        uint32_t nH = sb + (uint32_t)((g + 1) & 1) * 2u * STAGE_BYTES;
        uint32_t nL = nH + STAGE_BYTES;
        const int dfn = g * D;

        #pragma unroll
        for (int kt = 0; kt < 3; kt++) {
            int tap = g * 3 + kt;
            const uint4* wb = wfbase + (size_t)tap * 1024;
            uint32_t abase = pfoff + (uint32_t)(kt * D) * AT_STRIDE + laneoff;

            #pragma unroll
            for (int ks = 0; ks < 4; ks++) {
                uint32_t bh[4][2], bl[4][2];
                #pragma unroll
                for (int n = 0; n < 4; n++) {
                    bh[n][0] = qbuf[n].x; bh[n][1] = qbuf[n].y;
                    bl[n][0] = qbuf[n].z; bl[n][1] = qbuf[n].w;
                }
                if (!((g == 2) && (kt == 2) && (ks == 3))) {
                    const uint4* wbn = (ks < 3) ? wb : (wb + 1024);
                    int ksn = (ks < 3) ? (ks + 1) : 0;
                    #pragma unroll
                    for (int n = 0; n < 4; n++)
                        qbuf[n] = __ldg(&wbn[(ksn * 8 + n8b + n) * 32 + lid]);
                }

                uint32_t ah[2][4], al[2][4];
                ldmx4(ah[0], aH + abase + ks * 32);
                ldmx4(ah[1], aH + abase + 16 * AT_STRIDE + ks * 32);
                ldmx4(al[0], aL + abase + ks * 32);
                ldmx4(al[1], aL + abase + 16 * AT_STRIDE + ks * 32);

                #pragma unroll
                for (int m = 0; m < 2; m++)
                    #pragma unroll
                    for (int n = 0; n < 4; n++) hmma(acc[m][n], ah[m], bh[n]);
                #pragma unroll
                for (int m = 0; m < 2; m++)
                    #pragma unroll
                    for (int n = 0; n < 4; n++) hmma(acc[m][n], ah[m], bl[n]);
                #pragma unroll
                for (int m = 0; m < 2; m++)
                    #pragma unroll
                    for (int n = 0; n < 4; n++) hmma(acc[m][n], al[m], bh[n]);

                // FRONT-LOADED interleaved loads: 2 chunks/iter during iters 0..5
                if (g < 2) {
                    int it = kt * 4 + ks;
                    if (it < 6) {
                        #pragma unroll
                        for (int c = 0; c < 2; c++) {
                            int e = (it * 2 + c) * 256 + tid;
                            if (e < E) {
                                int pf = e / HW8;
                                int r = e - pf * HW8;
                                int tl = r >> 3, cb = (r & 7) * 16;
                                int gf = f0 + pf + dfn, gt = t0 - D + tl;
                                bool ok = ((unsigned)gf < F_DIM) && ((unsigned)gt < T_DIM);
                                size_t ridx = ok ? ((((size_t)b * F_DIM + gf) * T_DIM + gt) * 64) : 0;
                                uint32_t off = (uint32_t)(pf * 48 + tl) * AT_STRIDE + cb;
                                cp16(nH + off, (const unsigned char*)inH + ridx * 2 + cb, ok ? 16 : 0);
                                cp16(nL + off, (const unsigned char*)inL + ridx * 2 + cb, ok ? 16 : 0);
                            }
                        }
                    }
                }
            }
        }
        if (g < 2) CP_COMMIT();
    }
    __syncthreads();

    const float* bias = reinterpret_cast<const float*>(smem + SM_BIAS_OFF);

    if (LAST) {
        // ---- finale: stage fp32 rows in smem (272B stride), then coalesced writeout ----
        float* fst = reinterpret_cast<float*>(smem);
        #pragma unroll
        for (int m = 0; m < 2; m++) {
            #pragma unroll
            for (int r2 = 0; r2 < 2; r2++) {
                int p = mrow0 + m * 16 + (lid >> 2) + r2 * 8;
                #pragma unroll
                for (int n = 0; n < 4; n++) {
                    int oc = ocw + n * 8 + (lid & 3) * 2;
                    float y0 = acc[m][n][r2 * 2 + 0] + bias[oc];
                    float y1 = acc[m][n][r2 * 2 + 1] + bias[oc + 1];
                    y0 = (y0 > 0.f) ? y0 : SLOPE * y0;
                    y1 = (y1 > 0.f) ? y1 : SLOPE * y1;
                    *reinterpret_cast<float2*>(fst + p * 68 + oc) = make_float2(y0, y1);
                }
            }
        }
        __syncthreads();
        #pragma unroll
        for (int i0 = 0; i0 < 2048; i0 += 256) {
            int i = i0 + tid;
            int p = i >> 4, col = i & 15;
            int gf = f0 + (p >> 5), gt = t0 + (p & 31);
            if (gf < F_DIM && gt < T_DIM) {
                float4 v = *reinterpret_cast<const float4*>(fst + p * 68 + col * 4);
                size_t ridx = (((size_t)b * F_DIM + gf) * T_DIM + gt) * 64 + col * 4;
                *reinterpret_cast<float4*>(d_afin + ridx) = v;
            }
        }
    } else {
        // ---- epilogue: bias + leaky + hi/lo split, stmatrix staging, coalesced STG.128 ----
        uint32_t stg = sb + (uint32_t)wid * 5120u;
        unsigned char* stgp = smem + wid * 5120;

        #pragma unroll
        for (int m = 0; m < 2; m++) {
            uint32_t hreg[2][4], lreg[2][4];
            #pragma unroll
            for (int n = 0; n < 4; n++) {
                int oc = ocw + n * 8 + (lid & 3) * 2;
                float b0 = bias[oc], b1 = bias[oc + 1];
                #pragma unroll
                for (int r2 = 0; r2 < 2; r2++) {
                    float y0 = acc[m][n][r2 * 2 + 0] + b0;
                    float y1 = acc[m][n][r2 * 2 + 1] + b1;
                    y0 = (y0 > 0.f) ? y0 : SLOPE * y0;
                    y1 = (y1 > 0.f) ? y1 : SLOPE * y1;
                    float h0 = __bfloat162float(__float2bfloat16(y0));
                    float h1 = __bfloat162float(__float2bfloat16(y1));
                    hreg[r2][n] = pack_bf2(h0, h1);
                    lreg[r2][n] = pack_bf2(y0 - h0, y1 - h1);
                }
            }
            uint32_t arow = stg + (uint32_t)((m * 16 + rowin) * 80 + mat * 16);
            stmx4(arow,                 hreg[0]);
            stmx4(arow + 8 * 80,        hreg[1]);
            stmx4(arow + 2560,          lreg[0]);
            stmx4(arow + 2560 + 8 * 80, lreg[1]);
        }
        __syncwarp();

        int gfx = f0 + (wid & 3);
        if (gfx < F_DIM) {
            #pragma unroll
            for (int it = 0; it < 4; it++) {
                int p = it * 8 + (lid >> 2);
                int gt = t0 + p;
                uint4 vh = *reinterpret_cast<const uint4*>(stgp + p * 80 + (lid & 3) * 16);
                uint4 vl = *reinterpret_cast<const uint4*>(stgp + 2560 + p * 80 + (lid & 3) * 16);
                if (gt < T_DIM) {
                    size_t ridx = (((size_t)b * F_DIM + gfx) * T_DIM + gt) * 64 + ocw + (lid & 3) * 8;
                    *reinterpret_cast<uint4*>(outH + ridx) = vh;
                    *reinterpret_cast<uint4*>(outL + ridx) = vl;
                }
            }
        }
    }
}

// ======================= last conv (64 -> 1, 3x3, pad 1): fp32 smem-tiled =======================
#define L2_STRIDE 272
#define L2_PX 340
#define L2_SW (L2_PX * L2_STRIDE)
#define L2_SMEM (L2_SW + 2320)

__global__ __launch_bounds__(256, 2) void last_kernel(float* __restrict__ out) {
    extern __shared__ __align__(16) unsigned char lsm[];
    uint32_t sbx = smem_u32(lsm);
    float* sw = reinterpret_cast<float*>(lsm + L2_SW);
    int tid = threadIdx.x;
    int t0 = blockIdx.x * 32, f0 = blockIdx.y * 8, b = blockIdx.z;

    for (int i = tid; i < 577; i += 256) sw[i] = d_wl[i];

    for (int e = tid; e < L2_PX * 16; e += 256) {
        int p = e >> 4, cb = (e & 15) * 16;
        int fl = p / 34, tl = p - fl * 34;
        int gf = f0 - 1 + fl, gt = t0 - 1 + tl;
        bool ok = ((unsigned)gf < F_DIM) && ((unsigned)gt < T_DIM);
        size_t ridx = ok ? ((((size_t)b * F_DIM + gf) * T_DIM + gt) * 64) : 0;
        cp16(sbx + p * L2_STRIDE + cb, (const unsigned char*)d_afin + ridx * 4 + cb, ok ? 16 : 0);
    }
    CP_COMMIT(); CP_WAIT(0);
    __syncthreads();

    int fl = tid >> 5, tl = tid & 31;
    int f = f0 + fl, t = t0 + tl;
    if (f >= F_DIM || t >= T_DIM) return;

    float acc = sw[576];
    #pragma unroll
    for (int kf = 0; kf < 3; kf++) {
        #pragma unroll
        for (int kt = 0; kt < 3; kt++) {
            int p = (fl + kf) * 34 + (tl + kt);
            const float4* px = reinterpret_cast<const float4*>(lsm + p * L2_STRIDE);
            int wi = kf * 3 + kt;
            #pragma unroll
            for (int c4 = 0; c4 < 16; c4++) {
                float4 v = px[c4];
                int c = c4 * 4;
                acc += v.x * sw[c * 9 + wi];
                acc += v.y * sw[(c + 1) * 9 + wi];
                acc += v.z * sw[(c + 2) * 9 + wi];
                acc += v.w * sw[(c + 3) * 9 + wi];
            }
        }
    }
    out[(size_t)b * NPIX + (size_t)f * T_DIM + t] = acc;
}

// ======================= launch =======================
extern "C" void kernel_launch(void* const* d_in, const int* in_sizes, int n_in,
                              void* d_out, int out_size) {
    const float* x      = (const float*)d_in[0];
    const float* v_h    = (const float*)d_in[1];
    const float* g_h    = (const float*)d_in[2];
    const float* b_h    = (const float*)d_in[3];
    const float* vs     = (const float*)d_in[4];
    const float* gs     = (const float*)d_in[5];
    const float* bs     = (const float*)d_in[6];
    const float* v_last = (const float*)d_in[7];
    const float* g_last = (const float*)d_in[8];
    const float* b_last = (const float*)d_in[9];
    float* out = (float*)d_out;

    cudaFuncSetAttribute(conv3_mma<1, false>, cudaFuncAttributeMaxDynamicSharedMemorySize, CONV3_SMEM);
    cudaFuncSetAttribute(conv3_mma<2, false>, cudaFuncAttributeMaxDynamicSharedMemorySize, CONV3_SMEM);
    cudaFuncSetAttribute(conv3_mma<3, false>, cudaFuncAttributeMaxDynamicSharedMemorySize, CONV3_SMEM);
    cudaFuncSetAttribute(conv3_mma<4, false>, cudaFuncAttributeMaxDynamicSharedMemorySize, CONV3_SMEM);
    cudaFuncSetAttribute(conv3_mma<5, false>, cudaFuncAttributeMaxDynamicSharedMemorySize, CONV3_SMEM);
    cudaFuncSetAttribute(conv3_mma<6, false>, cudaFuncAttributeMaxDynamicSharedMemorySize, CONV3_SMEM);
    cudaFuncSetAttribute(conv3_mma<7, false>, cudaFuncAttributeMaxDynamicSharedMemorySize, CONV3_SMEM);
    cudaFuncSetAttribute(conv3_mma<8, true>,  cudaFuncAttributeMaxDynamicSharedMemorySize, CONV3_SMEM);
    cudaFuncSetAttribute(last_kernel, cudaFuncAttributeMaxDynamicSharedMemorySize, L2_SMEM);

    prep_kernel<<<578, 128>>>(v_h, g_h, vs, gs, v_last, g_last, b_last);
    stft_kernel<<<dim3(257, NB), 256>>>(x);
    conv1_kernel<<<(NTOT + 127) / 128, 256>>>(b_h);

    dim3 cg(9, 65, NB);
    conv3_mma<1, false><<<cg, 256, CONV3_SMEM>>>(0, bs);
    conv3_mma<2, false><<<cg, 256, CONV3_SMEM>>>(1, bs);
    conv3_mma<3, false><<<cg, 256, CONV3_SMEM>>>(2, bs);
    conv3_mma<4, false><<<cg, 256, CONV3_SMEM>>>(3, bs);
    conv3_mma<5, false><<<cg, 256, CONV3_SMEM>>>(4, bs);
    conv3_mma<6, false><<<cg, 256, CONV3_SMEM>>>(5, bs);
    conv3_mma<7, false><<<cg, 256, CONV3_SMEM>>>(6, bs);
    conv3_mma<8, true><<<cg, 256, CONV3_SMEM>>>(7, bs);

    last_kernel<<<dim3(9, 33, NB), 256, L2_SMEM>>>(out);
}